// round 12
// baseline (speedup 1.0000x reference)
#include <cuda_runtime.h>
#include <cuda_bf16.h>
#include <math.h>

#define NN 100000
#define EE 1600000
#define FIN 128
#define HID 32
#define HEADS 8
#define D1 256        // HEADS*HID
#define NCLS 40
#define BETA 0.1f
#define ONE_MB 0.9f   // 1-beta
#define LRA 0.2f      // leaky relu alpha
#define SCB 1024
#define NBLK ((NN + SCB - 1) / SCB)

// ------------- scratch (device globals; total ~237 MB, < 256 MB) -------------
__device__ __align__(128) float g_H0[(size_t)NN * D1];    // x@Wcat; layer-1 out in place
__device__ __align__(128) float g_FA[(size_t)NN * 128];   // hop-1 scratch; reused as GA
__device__ __align__(128) float g_O0[(size_t)NN * NCLS];  // H @ W_out
__device__ __align__(128) float g_WBUF[2][(size_t)EE * 4];// unnorm attn w, group-packed
__device__ __align__(128) int   g_SSRC[EE];               // src sorted by dst (CSR)
__device__ __align__(128) float g_S8[(size_t)NN * 8];
__device__ __align__(128) float g_T8[(size_t)NN * 8];
__device__ __align__(128) float g_INV8[(size_t)NN * 8];
__device__ int   g_ROWPTR[NN + 1];
__device__ int   g_DEG[NN];
__device__ int   g_CUR[NN];
__device__ int   g_BSUM[NBLK];
__device__ int   g_BOFF[NBLK];
__device__ int   g_EI64;

// ------------------------------- helpers --------------------------------------
__device__ __forceinline__ float warp_sum(float v) {
#pragma unroll
    for (int o = 16; o > 0; o >>= 1) v += __shfl_xor_sync(0xffffffffu, v, o);
    return v;
}
__device__ __forceinline__ float warp_max(float v) {
#pragma unroll
    for (int o = 16; o > 0; o >>= 1) v = fmaxf(v, __shfl_xor_sync(0xffffffffu, v, o));
    return v;
}
__device__ __forceinline__ int warp_sum_i(int v) {
#pragma unroll
    for (int o = 16; o > 0; o >>= 1) v += __shfl_xor_sync(0xffffffffu, v, o);
    return v;
}
__device__ __forceinline__ float sel4(float4 w, int h) {
    return (h == 0) ? w.x : (h == 1) ? w.y : (h == 2) ? w.z : w.w;
}

// ---- packed f32x2 FMA (sm_103a FFMA2 — full-rate fp32, vs half-rate FFMA.3reg)
__device__ __forceinline__ unsigned long long pack2(float lo, float hi) {
    unsigned long long r;
    asm("mov.b64 %0, {%1, %2};" : "=l"(r) : "f"(lo), "f"(hi));
    return r;
}
__device__ __forceinline__ float2 unpack2(unsigned long long v) {
    float2 r;
    asm("mov.b64 {%0, %1}, %2;" : "=f"(r.x), "=f"(r.y) : "l"(v));
    return r;
}
__device__ __forceinline__ void ffma2(unsigned long long& d,
                                      unsigned long long a,
                                      unsigned long long b) {
    asm("fma.rn.f32x2 %0, %1, %2, %0;" : "+l"(d) : "l"(a), "l"(b));
}

// ------------------------- edge dtype sniff (parallel) -------------------------
__global__ void sniff_kernel(const int* __restrict__ ei32) {
    int bad = 0;
    for (int i = threadIdx.x; i < 512; i += 256)
        bad |= (ei32[2 * i + 1] != 0);
    bad = __syncthreads_or(bad);
    if (threadIdx.x == 0) g_EI64 = bad ? 0 : 1;
}

__device__ __forceinline__ int load_node(const void* ei, size_t pos, int is64) {
    if (is64) return (int)((const long long*)ei)[pos];
    return ((const int*)ei)[pos];
}

// ------------------------------ CSR build -------------------------------------
__global__ void zero_counts_kernel() {
    int i = blockIdx.x * blockDim.x + threadIdx.x;
    if (i < NN) { g_DEG[i] = 0; g_CUR[i] = 0; }
}

__global__ void build_deg_kernel(const void* __restrict__ ei) {
    int e = blockIdx.x * blockDim.x + threadIdx.x;
    if (e >= EE) return;
    int d = load_node(ei, (size_t)EE + e, g_EI64);
    if ((unsigned)d < NN) atomicAdd(&g_DEG[d], 1);
}

__global__ void scanA_kernel() {
    __shared__ int wsum[8];
    int tid = threadIdx.x;
    int base = blockIdx.x * SCB + tid * 4;
    int s = 0;
#pragma unroll
    for (int j = 0; j < 4; j++) { int i = base + j; if (i < NN) s += g_DEG[i]; }
    s = warp_sum_i(s);
    if ((tid & 31) == 0) wsum[tid >> 5] = s;
    __syncthreads();
    if (tid == 0) {
        int t = 0;
#pragma unroll
        for (int w = 0; w < 8; w++) t += wsum[w];
        g_BSUM[blockIdx.x] = t;
    }
}

__global__ void scanB_kernel() {
    __shared__ int sm[4];
    int tid = threadIdx.x, lane = tid & 31, wid = tid >> 5;
    int v = (tid < NBLK) ? g_BSUM[tid] : 0;
    int x = v;
#pragma unroll
    for (int o = 1; o < 32; o <<= 1) {
        int y = __shfl_up_sync(0xffffffffu, x, o);
        if (lane >= o) x += y;
    }
    if (lane == 31) sm[wid] = x;
    __syncthreads();
    int woff = 0;
    for (int w = 0; w < wid; w++) woff += sm[w];
    if (tid < NBLK) g_BOFF[tid] = woff + x - v;
}

__global__ void scanC_kernel() {
    __shared__ int wsum[8];
    int tid = threadIdx.x, lane = tid & 31, wid = tid >> 5;
    int base = blockIdx.x * SCB + tid * 4;
    int a0 = (base + 0 < NN) ? g_DEG[base + 0] : 0;
    int a1 = (base + 1 < NN) ? g_DEG[base + 1] : 0;
    int a2 = (base + 2 < NN) ? g_DEG[base + 2] : 0;
    int a3 = (base + 3 < NN) ? g_DEG[base + 3] : 0;
    int tsum = a0 + a1 + a2 + a3;
    int x = tsum;
#pragma unroll
    for (int o = 1; o < 32; o <<= 1) {
        int y = __shfl_up_sync(0xffffffffu, x, o);
        if (lane >= o) x += y;
    }
    if (lane == 31) wsum[wid] = x;
    __syncthreads();
    int woff = 0;
    for (int w = 0; w < wid; w++) woff += wsum[w];
    int excl = g_BOFF[blockIdx.x] + woff + (x - tsum);
    if (base + 0 < NN) g_ROWPTR[base + 1] = excl + a0;
    if (base + 1 < NN) g_ROWPTR[base + 2] = excl + a0 + a1;
    if (base + 2 < NN) g_ROWPTR[base + 3] = excl + a0 + a1 + a2;
    if (base + 3 < NN) g_ROWPTR[base + 4] = excl + tsum;
    if (blockIdx.x == 0 && tid == 0) g_ROWPTR[0] = 0;
}

__global__ void scatter_kernel(const void* __restrict__ ei) {
    int e = blockIdx.x * blockDim.x + threadIdx.x;
    if (e >= EE) return;
    int is64 = g_EI64;
    int s = load_node(ei, (size_t)e, is64);
    int d = load_node(ei, (size_t)EE + e, is64);
    if ((unsigned)d >= NN || (unsigned)s >= NN) return;
    int pos = g_ROWPTR[d] + atomicAdd(&g_CUR[d], 1);
    if ((unsigned)pos < EE) g_SSRC[pos] = s;
}

// ---------------- GEMM1: 128x128 block, 8x8/thread, FFMA2 inner ---------------
__global__ void __launch_bounds__(256) gemm1_kernel(const float* __restrict__ x,
                                                    const float* __restrict__ W) {
    __shared__ float As[16][132];
    __shared__ float Bs[16][132];
    int tid = threadIdx.x;
    int tx = tid & 15;
    int ty = tid >> 4;
    int rowBase = blockIdx.x * 128;
    int colBase = blockIdx.y * 128;
    unsigned long long acc2[8][4] = {};   // [row][col-pair]
    for (int kt = 0; kt < FIN; kt += 16) {
#pragma unroll
        for (int p = 0; p < 2; p++) {
            int idx = tid + p * 256;
            int r = idx & 127;
            int kq = idx >> 7;
            int gr = rowBase + r;
            float4 v = make_float4(0.f, 0.f, 0.f, 0.f);
            if (gr < NN) v = *(const float4*)&x[(size_t)gr * FIN + kt + kq * 4];
            As[kq * 4 + 0][r] = v.x;
            As[kq * 4 + 1][r] = v.y;
            As[kq * 4 + 2][r] = v.z;
            As[kq * 4 + 3][r] = v.w;
        }
#pragma unroll
        for (int p = 0; p < 2; p++) {
            int idx = tid + p * 256;
            int k = idx >> 5;
            int q = idx & 31;
            int col = colBase + q * 4;
            float4 v = *(const float4*)&W[(size_t)(col >> 5) * (FIN * HID)
                                          + (size_t)(kt + k) * HID + (col & 31)];
            *(float4*)&Bs[k][q * 4] = v;
        }
        __syncthreads();
#pragma unroll
        for (int k = 0; k < 16; k++) {
            float4 a0 = *(const float4*)&As[k][ty * 8];
            float4 a1 = *(const float4*)&As[k][ty * 8 + 4];
            float4 b0 = *(const float4*)&Bs[k][tx * 8];
            float4 b1 = *(const float4*)&Bs[k][tx * 8 + 4];
            unsigned long long bp0 = pack2(b0.x, b0.y);
            unsigned long long bp1 = pack2(b0.z, b0.w);
            unsigned long long bp2 = pack2(b1.x, b1.y);
            unsigned long long bp3 = pack2(b1.z, b1.w);
            float am[8] = {a0.x, a0.y, a0.z, a0.w, a1.x, a1.y, a1.z, a1.w};
#pragma unroll
            for (int i = 0; i < 8; i++) {
                unsigned long long ad = pack2(am[i], am[i]);
                ffma2(acc2[i][0], ad, bp0);
                ffma2(acc2[i][1], ad, bp1);
                ffma2(acc2[i][2], ad, bp2);
                ffma2(acc2[i][3], ad, bp3);
            }
        }
        __syncthreads();
    }
#pragma unroll
    for (int i = 0; i < 8; i++) {
        int gr = rowBase + ty * 8 + i;
        if (gr < NN) {
            float2 c0 = unpack2(acc2[i][0]);
            float2 c1 = unpack2(acc2[i][1]);
            float2 c2 = unpack2(acc2[i][2]);
            float2 c3 = unpack2(acc2[i][3]);
            *(float4*)&g_H0[(size_t)gr * D1 + colBase + tx * 8] =
                make_float4(c0.x, c0.y, c1.x, c1.y);
            *(float4*)&g_H0[(size_t)gr * D1 + colBase + tx * 8 + 4] =
                make_float4(c2.x, c2.y, c3.x, c3.y);
        }
    }
}

// ------------- GEMM2 (FFMA2) + fused st40 (s,t for output layer) --------------
__global__ void gemm2_kernel(const float* __restrict__ Wout,
                             const float* __restrict__ a_so,
                             const float* __restrict__ a_do) {
    __shared__ float Bs[D1 * NCLS];
    __shared__ float As_[NCLS], Ad_[NCLS];
    int tid = threadIdx.x;
    for (int i = tid; i < D1 * NCLS; i += 256) Bs[i] = Wout[i];
    if (tid < NCLS) { As_[tid] = a_so[tid]; Ad_[tid] = a_do[tid]; }
    __syncthreads();
    int row = blockIdx.x * 256 + tid;
    if (row >= NN) return;
    const float* arow = g_H0 + (size_t)row * D1;
    unsigned long long acc2[20] = {};
#pragma unroll 2
    for (int k = 0; k < D1; k++) {
        float a = __ldg(arow + k);
        unsigned long long ad = pack2(a, a);
        const ulonglong2* b2 = (const ulonglong2*)&Bs[k * NCLS];  // 160B rows, 16B-aligned
#pragma unroll
        for (int j = 0; j < 10; j++) {
            ulonglong2 bb = b2[j];
            ffma2(acc2[2 * j + 0], ad, bb.x);
            ffma2(acc2[2 * j + 1], ad, bb.y);
        }
    }
    float accf[NCLS];
#pragma unroll
    for (int j = 0; j < 20; j++) {
        float2 u = unpack2(acc2[j]);
        accf[2 * j] = u.x;
        accf[2 * j + 1] = u.y;
    }
    float* orow = g_O0 + (size_t)row * NCLS;
    float s = 0.f, t = 0.f;
#pragma unroll
    for (int c = 0; c < NCLS; c++) {
        orow[c] = accf[c];
        s += accf[c] * As_[c];
        t += accf[c] * Ad_[c];
    }
    g_S8[row] = s;     // stride-1 reuse for output layer
    g_T8[row] = t;
}

// --------------------- attention s,t for ALL 8 heads at once ------------------
__global__ void st8_kernel(const float* __restrict__ a_src,
                           const float* __restrict__ a_dst) {
    int gw = blockIdx.x * 8 + (threadIdx.x >> 5);
    int lane = threadIdx.x & 31;
    if (gw >= NN) return;
    const float* row = g_H0 + (size_t)gw * D1;
#pragma unroll
    for (int h = 0; h < HEADS; h++) {
        float v = row[h * HID + lane];
        float s = warp_sum(v * a_src[h * HID + lane]);
        float t = warp_sum(v * a_dst[h * HID + lane]);
        if (lane == 0) { g_S8[(size_t)gw * 8 + h] = s; g_T8[(size_t)gw * 8 + h] = t; }
    }
}

// ------------ 8-head fused attention weights (unnormalized) + INV --------------
__global__ void attn8_kernel() {
    int d = blockIdx.x * 8 + (threadIdx.x >> 5);
    int lane = threadIdx.x & 31;
    if (d >= NN) return;
    int start = g_ROWPTR[d], end = g_ROWPTR[d + 1];
    if (start == end) {
        if (lane == 0) {
            float4 z = make_float4(0.f, 0.f, 0.f, 0.f);
            *(float4*)&g_INV8[(size_t)d * 8] = z;
            *(float4*)&g_INV8[(size_t)d * 8 + 4] = z;
        }
        return;
    }
    float4 ta = *(const float4*)&g_T8[(size_t)d * 8];
    float4 tb = *(const float4*)&g_T8[(size_t)d * 8 + 4];
    float t[8] = {ta.x, ta.y, ta.z, ta.w, tb.x, tb.y, tb.z, tb.w};
    float m[8];
#pragma unroll
    for (int i = 0; i < 8; i++) m[i] = -INFINITY;
    for (int e = start + lane; e < end; e += 32) {
        int s = g_SSRC[e];
        float4 sa = *(const float4*)&g_S8[(size_t)s * 8];
        float4 sb = *(const float4*)&g_S8[(size_t)s * 8 + 4];
        float sv[8] = {sa.x, sa.y, sa.z, sa.w, sb.x, sb.y, sb.z, sb.w};
#pragma unroll
        for (int i = 0; i < 8; i++) {
            float ev = sv[i] + t[i];
            ev = (ev >= 0.f) ? ev : LRA * ev;
            m[i] = fmaxf(m[i], ev);
        }
    }
#pragma unroll
    for (int i = 0; i < 8; i++) m[i] = warp_max(m[i]);
    float u[8] = {};
    for (int e = start + lane; e < end; e += 32) {
        int s = g_SSRC[e];
        float4 sa = *(const float4*)&g_S8[(size_t)s * 8];
        float4 sb = *(const float4*)&g_S8[(size_t)s * 8 + 4];
        float sv[8] = {sa.x, sa.y, sa.z, sa.w, sb.x, sb.y, sb.z, sb.w};
        float p[8];
#pragma unroll
        for (int i = 0; i < 8; i++) {
            float ev = sv[i] + t[i];
            ev = (ev >= 0.f) ? ev : LRA * ev;
            p[i] = expf(ev - m[i]);
            u[i] += p[i];
        }
        *(float4*)&g_WBUF[0][(size_t)e * 4] = make_float4(p[0], p[1], p[2], p[3]);
        *(float4*)&g_WBUF[1][(size_t)e * 4] = make_float4(p[4], p[5], p[6], p[7]);
    }
#pragma unroll
    for (int i = 0; i < 8; i++) u[i] = warp_sum(u[i]);
    if (lane == 0) {
        *(float4*)&g_INV8[(size_t)d * 8] =
            make_float4(1.f / (u[0] + 1e-16f), 1.f / (u[1] + 1e-16f),
                        1.f / (u[2] + 1e-16f), 1.f / (u[3] + 1e-16f));
        *(float4*)&g_INV8[(size_t)d * 8 + 4] =
            make_float4(1.f / (u[4] + 1e-16f), 1.f / (u[5] + 1e-16f),
                        1.f / (u[6] + 1e-16f), 1.f / (u[7] + 1e-16f));
    }
}

// ------------------ 4-head fused diffusion hop (warp per dst) -----------------
__global__ void hop4_kernel(int g, int mode) {
    int d = blockIdx.x * 8 + (threadIdx.x >> 5);
    int lane = threadIdx.x & 31;
    if (d >= NN) return;
    int h = lane >> 3;
    int start = g_ROWPTR[d], end = g_ROWPTR[d + 1];
    const float* wb = g_WBUF[g];
    float4 acc = make_float4(0.f, 0.f, 0.f, 0.f);
    int e = start;
    for (; e + 4 <= end; e += 4) {
        int s0 = g_SSRC[e], s1 = g_SSRC[e + 1], s2 = g_SSRC[e + 2], s3 = g_SSRC[e + 3];
        float4 w0 = *(const float4*)&wb[(size_t)e * 4];
        float4 w1 = *(const float4*)&wb[(size_t)(e + 1) * 4];
        float4 w2 = *(const float4*)&wb[(size_t)(e + 2) * 4];
        float4 w3 = *(const float4*)&wb[(size_t)(e + 3) * 4];
        const float4 *r0, *r1, *r2, *r3;
        if (mode == 0) {
            r0 = (const float4*)(g_H0 + (size_t)s0 * D1 + g * 128);
            r1 = (const float4*)(g_H0 + (size_t)s1 * D1 + g * 128);
            r2 = (const float4*)(g_H0 + (size_t)s2 * D1 + g * 128);
            r3 = (const float4*)(g_H0 + (size_t)s3 * D1 + g * 128);
        } else {
            r0 = (const float4*)(g_FA + (size_t)s0 * 128);
            r1 = (const float4*)(g_FA + (size_t)s1 * 128);
            r2 = (const float4*)(g_FA + (size_t)s2 * 128);
            r3 = (const float4*)(g_FA + (size_t)s3 * 128);
        }
        float4 v0 = r0[lane], v1 = r1[lane], v2 = r2[lane], v3 = r3[lane];
        float wv0 = sel4(w0, h), wv1 = sel4(w1, h), wv2 = sel4(w2, h), wv3 = sel4(w3, h);
        acc.x += wv0 * v0.x + wv1 * v1.x + wv2 * v2.x + wv3 * v3.x;
        acc.y += wv0 * v0.y + wv1 * v1.y + wv2 * v2.y + wv3 * v3.y;
        acc.z += wv0 * v0.z + wv1 * v1.z + wv2 * v2.z + wv3 * v3.z;
        acc.w += wv0 * v0.w + wv1 * v1.w + wv2 * v2.w + wv3 * v3.w;
    }
    for (; e < end; e++) {
        int s0 = g_SSRC[e];
        float4 w0 = *(const float4*)&wb[(size_t)e * 4];
        const float4* r0 = (mode == 0)
            ? (const float4*)(g_H0 + (size_t)s0 * D1 + g * 128)
            : (const float4*)(g_FA + (size_t)s0 * 128);
        float4 v0 = r0[lane];
        float wv0 = sel4(w0, h);
        acc.x += wv0 * v0.x; acc.y += wv0 * v0.y;
        acc.z += wv0 * v0.z; acc.w += wv0 * v0.w;
    }
    float4 inv4 = *(const float4*)&g_INV8[(size_t)d * 8 + g * 4];
    float invv = sel4(inv4, h);
    const float4* h0r = (const float4*)(g_H0 + (size_t)d * D1 + g * 128);
    float4 h0v = h0r[lane];
    float4 v;
    v.x = ONE_MB * acc.x * invv + BETA * h0v.x;
    v.y = ONE_MB * acc.y * invv + BETA * h0v.y;
    v.z = ONE_MB * acc.z * invv + BETA * h0v.z;
    v.w = ONE_MB * acc.w * invv + BETA * h0v.w;
    if (mode == 0) {
        ((float4*)(g_FA + (size_t)d * 128))[lane] = v;
    } else {
        v.x = (v.x > 0.f) ? v.x : expm1f(v.x);
        v.y = (v.y > 0.f) ? v.y : expm1f(v.y);
        v.z = (v.z > 0.f) ? v.z : expm1f(v.z);
        v.w = (v.w > 0.f) ? v.w : expm1f(v.w);
        ((float4*)(g_H0 + (size_t)d * D1 + g * 128))[lane] = v;
    }
}

// ------------------------------ output layer -----------------------------------
__global__ void attn_w_kernel() {      // normalized weights into g_WBUF[0]
    int d = blockIdx.x * 8 + (threadIdx.x >> 5);
    int lane = threadIdx.x & 31;
    if (d >= NN) return;
    int start = g_ROWPTR[d], end = g_ROWPTR[d + 1];
    if (start == end) return;
    float* wb = g_WBUF[0];
    float td = g_T8[d];
    float m = -INFINITY;
    for (int e = start + lane; e < end; e += 32) {
        float ev = g_S8[g_SSRC[e]] + td;
        ev = (ev >= 0.f) ? ev : LRA * ev;
        m = fmaxf(m, ev);
    }
    m = warp_max(m);
    float sum = 0.f;
    for (int e = start + lane; e < end; e += 32) {
        float ev = g_S8[g_SSRC[e]] + td;
        ev = (ev >= 0.f) ? ev : LRA * ev;
        float p = expf(ev - m);
        wb[e] = p;
        sum += p;
    }
    sum = warp_sum(sum);
    float inv = 1.f / (sum + 1e-16f);
    for (int e = start + lane; e < end; e += 32) wb[e] *= inv;
}

__global__ void hop40_kernel(int mode, float* __restrict__ out) {
    int d = blockIdx.x * 8 + (threadIdx.x >> 5);
    int lane = threadIdx.x & 31;
    if (d >= NN) return;
    int start = g_ROWPTR[d], end = g_ROWPTR[d + 1];
    float acca = 0.f, accb = 0.f;
    bool hi = (lane < 8);
    const float* base = (mode == 0) ? g_O0 : g_FA;
    const float* wb = g_WBUF[0];
    int e = start;
    for (; e + 4 <= end; e += 4) {
        int s0 = g_SSRC[e], s1 = g_SSRC[e + 1], s2 = g_SSRC[e + 2], s3 = g_SSRC[e + 3];
        float w0 = wb[e], w1 = wb[e + 1], w2 = wb[e + 2], w3 = wb[e + 3];
        const float* r0 = base + (size_t)s0 * NCLS;
        const float* r1 = base + (size_t)s1 * NCLS;
        const float* r2 = base + (size_t)s2 * NCLS;
        const float* r3 = base + (size_t)s3 * NCLS;
        acca += w0 * r0[lane] + w1 * r1[lane] + w2 * r2[lane] + w3 * r3[lane];
        if (hi)
            accb += w0 * r0[32 + lane] + w1 * r1[32 + lane]
                  + w2 * r2[32 + lane] + w3 * r3[32 + lane];
    }
    for (; e < end; e++) {
        int s = g_SSRC[e];
        float w = wb[e];
        const float* row = base + (size_t)s * NCLS;
        acca += w * row[lane];
        if (hi) accb += w * row[32 + lane];
    }
    const float* h0row = g_O0 + (size_t)d * NCLS;
    float va = ONE_MB * acca + BETA * h0row[lane];
    float vb = hi ? (ONE_MB * accb + BETA * h0row[32 + lane]) : 0.f;
    if (mode == 0) {
        float* orow = g_FA + (size_t)d * NCLS;
        orow[lane] = va;
        if (hi) orow[32 + lane] = vb;
    } else {
        float ea = (va > 0.f) ? va : expm1f(va);
        float eb = hi ? ((vb > 0.f) ? vb : expm1f(vb)) : -INFINITY;
        float mx = warp_max(fmaxf(ea, eb));
        float se = expf(ea - mx) + (hi ? expf(eb - mx) : 0.f);
        se = warp_sum(se);
        float lse = mx + logf(se);
        float* orow = out + (size_t)d * NCLS;
        orow[lane] = ea - lse;
        if (hi) orow[32 + lane] = eb - lse;
    }
}

// --------------------------------- launch -------------------------------------
extern "C" void kernel_launch(void* const* d_in, const int* in_sizes, int n_in,
                              void* d_out, int out_size) {
    const float* x     = (const float*)d_in[0];
    const void*  ei    = d_in[1];
    const float* W     = (const float*)d_in[2];
    const float* a_src = (const float*)d_in[3];
    const float* a_dst = (const float*)d_in[4];
    const float* Wout  = (const float*)d_in[5];
    const float* a_so  = (const float*)d_in[6];
    const float* a_do  = (const float*)d_in[7];
    float*       out   = (float*)d_out;

    const int NWARP_GRID = (NN + 7) / 8;
    const int EGRID = (EE + 255) / 256;
    const int NGRID = (NN + 255) / 256;

    sniff_kernel<<<1, 256>>>((const int*)ei);
    zero_counts_kernel<<<NGRID, 256>>>();
    build_deg_kernel<<<EGRID, 256>>>(ei);
    scanA_kernel<<<NBLK, 256>>>();
    scanB_kernel<<<1, 128>>>();
    scanC_kernel<<<NBLK, 256>>>();
    scatter_kernel<<<EGRID, 256>>>(ei);

    gemm1_kernel<<<dim3((NN + 127) / 128, D1 / 128), 256>>>(x, W);
    st8_kernel<<<NWARP_GRID, 256>>>(a_src, a_dst);
    attn8_kernel<<<NWARP_GRID, 256>>>();

    for (int g = 0; g < 2; g++) {
        hop4_kernel<<<NWARP_GRID, 256>>>(g, 0);
        hop4_kernel<<<NWARP_GRID, 256>>>(g, 1);
    }

    gemm2_kernel<<<(NN + 255) / 256, 256>>>(Wout, a_so, a_do);

    attn_w_kernel<<<NWARP_GRID, 256>>>();
    hop40_kernel<<<NWARP_GRID, 256>>>(0, nullptr);
    hop40_kernel<<<NWARP_GRID, 256>>>(1, out);
}

// round 13
// speedup vs baseline: 1.0736x; 1.0736x over previous
#include <cuda_runtime.h>
#include <cuda_fp16.h>
#include <math.h>

#define NN 100000
#define EE 1600000
#define FIN 128
#define HID 32
#define HEADS 8
#define D1 256        // HEADS*HID
#define NCLS 40
#define BETA 0.1f
#define ONE_MB 0.9f   // 1-beta
#define LRA 0.2f      // leaky relu alpha
#define SCB 1024
#define NBLK ((NN + SCB - 1) / SCB)

// ------------- scratch (device globals; total ~177 MB, < 256 MB) -------------
__device__ __align__(128) __half g_H16[(size_t)NN * D1];  // features fp16 (pre-diff, then final H)
__device__ __align__(128) __half g_FA16[(size_t)NN * 128];// hop-1 intermediate (fp16, per group)
__device__ __align__(128) float  g_O0[(size_t)NN * NCLS]; // H @ W_out (fp32)
__device__ __align__(128) float  g_GA[(size_t)NN * NCLS]; // layer-2 hop-1 (fp32)
__device__ __align__(128) float  g_WBUF[2][(size_t)EE * 4];// unnorm attn w (fp32)
__device__ __align__(128) int    g_SSRC[EE];              // src sorted by dst (CSR)
__device__ __align__(128) float  g_S8[(size_t)NN * 8];
__device__ __align__(128) float  g_T8[(size_t)NN * 8];
__device__ __align__(128) float  g_INV8[(size_t)NN * 8];
__device__ int   g_ROWPTR[NN + 1];
__device__ int   g_DEG[NN];
__device__ int   g_CUR[NN];
__device__ int   g_BSUM[NBLK];
__device__ int   g_BOFF[NBLK];
__device__ int   g_EI64;

// ------------------------------- helpers --------------------------------------
__device__ __forceinline__ float warp_sum(float v) {
#pragma unroll
    for (int o = 16; o > 0; o >>= 1) v += __shfl_xor_sync(0xffffffffu, v, o);
    return v;
}
__device__ __forceinline__ float warp_max(float v) {
#pragma unroll
    for (int o = 16; o > 0; o >>= 1) v = fmaxf(v, __shfl_xor_sync(0xffffffffu, v, o));
    return v;
}
__device__ __forceinline__ int warp_sum_i(int v) {
#pragma unroll
    for (int o = 16; o > 0; o >>= 1) v += __shfl_xor_sync(0xffffffffu, v, o);
    return v;
}
__device__ __forceinline__ float sel4(float4 w, int h) {
    return (h == 0) ? w.x : (h == 1) ? w.y : (h == 2) ? w.z : w.w;
}
// load 4 halves (8B) -> 4 floats
__device__ __forceinline__ float4 ld4h(const __half* p, int lane) {
    uint2 u = ((const uint2*)p)[lane];
    __half2 ha = *(__half2*)&u.x;
    __half2 hb = *(__half2*)&u.y;
    float2 f0 = __half22float2(ha);
    float2 f1 = __half22float2(hb);
    return make_float4(f0.x, f0.y, f1.x, f1.y);
}
// store 4 floats -> 4 halves (8B)
__device__ __forceinline__ void st4h(__half* p, int lane, float4 v) {
    __half2 pa = __floats2half2_rn(v.x, v.y);
    __half2 pb = __floats2half2_rn(v.z, v.w);
    uint2 u;
    u.x = *(unsigned*)&pa;
    u.y = *(unsigned*)&pb;
    ((uint2*)p)[lane] = u;
}

// ------------------------- edge dtype sniff (parallel) -------------------------
__global__ void sniff_kernel(const int* __restrict__ ei32) {
    int bad = 0;
    for (int i = threadIdx.x; i < 512; i += 256)
        bad |= (ei32[2 * i + 1] != 0);
    bad = __syncthreads_or(bad);
    if (threadIdx.x == 0) g_EI64 = bad ? 0 : 1;
}

__device__ __forceinline__ int load_node(const void* ei, size_t pos, int is64) {
    if (is64) return (int)((const long long*)ei)[pos];
    return ((const int*)ei)[pos];
}

// ------------------------------ CSR build -------------------------------------
__global__ void zero_counts_kernel() {
    int i = blockIdx.x * blockDim.x + threadIdx.x;
    if (i < NN) { g_DEG[i] = 0; g_CUR[i] = 0; }
}

__global__ void build_deg_kernel(const void* __restrict__ ei) {
    int e = blockIdx.x * blockDim.x + threadIdx.x;
    if (e >= EE) return;
    int d = load_node(ei, (size_t)EE + e, g_EI64);
    if ((unsigned)d < NN) atomicAdd(&g_DEG[d], 1);
}

__global__ void scanA_kernel() {
    __shared__ int wsum[8];
    int tid = threadIdx.x;
    int base = blockIdx.x * SCB + tid * 4;
    int s = 0;
#pragma unroll
    for (int j = 0; j < 4; j++) { int i = base + j; if (i < NN) s += g_DEG[i]; }
    s = warp_sum_i(s);
    if ((tid & 31) == 0) wsum[tid >> 5] = s;
    __syncthreads();
    if (tid == 0) {
        int t = 0;
#pragma unroll
        for (int w = 0; w < 8; w++) t += wsum[w];
        g_BSUM[blockIdx.x] = t;
    }
}

__global__ void scanB_kernel() {
    __shared__ int sm[4];
    int tid = threadIdx.x, lane = tid & 31, wid = tid >> 5;
    int v = (tid < NBLK) ? g_BSUM[tid] : 0;
    int x = v;
#pragma unroll
    for (int o = 1; o < 32; o <<= 1) {
        int y = __shfl_up_sync(0xffffffffu, x, o);
        if (lane >= o) x += y;
    }
    if (lane == 31) sm[wid] = x;
    __syncthreads();
    int woff = 0;
    for (int w = 0; w < wid; w++) woff += sm[w];
    if (tid < NBLK) g_BOFF[tid] = woff + x - v;
}

__global__ void scanC_kernel() {
    __shared__ int wsum[8];
    int tid = threadIdx.x, lane = tid & 31, wid = tid >> 5;
    int base = blockIdx.x * SCB + tid * 4;
    int a0 = (base + 0 < NN) ? g_DEG[base + 0] : 0;
    int a1 = (base + 1 < NN) ? g_DEG[base + 1] : 0;
    int a2 = (base + 2 < NN) ? g_DEG[base + 2] : 0;
    int a3 = (base + 3 < NN) ? g_DEG[base + 3] : 0;
    int tsum = a0 + a1 + a2 + a3;
    int x = tsum;
#pragma unroll
    for (int o = 1; o < 32; o <<= 1) {
        int y = __shfl_up_sync(0xffffffffu, x, o);
        if (lane >= o) x += y;
    }
    if (lane == 31) wsum[wid] = x;
    __syncthreads();
    int woff = 0;
    for (int w = 0; w < wid; w++) woff += wsum[w];
    int excl = g_BOFF[blockIdx.x] + woff + (x - tsum);
    if (base + 0 < NN) g_ROWPTR[base + 1] = excl + a0;
    if (base + 1 < NN) g_ROWPTR[base + 2] = excl + a0 + a1;
    if (base + 2 < NN) g_ROWPTR[base + 3] = excl + a0 + a1 + a2;
    if (base + 3 < NN) g_ROWPTR[base + 4] = excl + tsum;
    if (blockIdx.x == 0 && tid == 0) g_ROWPTR[0] = 0;
}

__global__ void scatter_kernel(const void* __restrict__ ei) {
    int e = blockIdx.x * blockDim.x + threadIdx.x;
    if (e >= EE) return;
    int is64 = g_EI64;
    int s = load_node(ei, (size_t)e, is64);
    int d = load_node(ei, (size_t)EE + e, is64);
    if ((unsigned)d >= NN || (unsigned)s >= NN) return;
    int pos = g_ROWPTR[d] + atomicAdd(&g_CUR[d], 1);
    if ((unsigned)pos < EE) g_SSRC[pos] = s;
}

// ------------- GEMM1: 128x128 block, 8x8/thread -> fp16 feature table ---------
__global__ void __launch_bounds__(256) gemm1_kernel(const float* __restrict__ x,
                                                    const float* __restrict__ W) {
    __shared__ float As[16][132];
    __shared__ float Bs[16][132];
    int tid = threadIdx.x;
    int tx = tid & 15;
    int ty = tid >> 4;
    int rowBase = blockIdx.x * 128;
    int colBase = blockIdx.y * 128;
    float acc[8][8] = {};
    for (int kt = 0; kt < FIN; kt += 16) {
#pragma unroll
        for (int p = 0; p < 2; p++) {
            int idx = tid + p * 256;
            int r = idx & 127;
            int kq = idx >> 7;
            int gr = rowBase + r;
            float4 v = make_float4(0.f, 0.f, 0.f, 0.f);
            if (gr < NN) v = *(const float4*)&x[(size_t)gr * FIN + kt + kq * 4];
            As[kq * 4 + 0][r] = v.x;
            As[kq * 4 + 1][r] = v.y;
            As[kq * 4 + 2][r] = v.z;
            As[kq * 4 + 3][r] = v.w;
        }
#pragma unroll
        for (int p = 0; p < 2; p++) {
            int idx = tid + p * 256;
            int k = idx >> 5;
            int q = idx & 31;
            int col = colBase + q * 4;
            float4 v = *(const float4*)&W[(size_t)(col >> 5) * (FIN * HID)
                                          + (size_t)(kt + k) * HID + (col & 31)];
            *(float4*)&Bs[k][q * 4] = v;
        }
        __syncthreads();
#pragma unroll
        for (int k = 0; k < 16; k++) {
            float4 a0 = *(const float4*)&As[k][ty * 8];
            float4 a1 = *(const float4*)&As[k][ty * 8 + 4];
            float4 b0 = *(const float4*)&Bs[k][tx * 8];
            float4 b1 = *(const float4*)&Bs[k][tx * 8 + 4];
            float am[8] = {a0.x, a0.y, a0.z, a0.w, a1.x, a1.y, a1.z, a1.w};
            float bn[8] = {b0.x, b0.y, b0.z, b0.w, b1.x, b1.y, b1.z, b1.w};
#pragma unroll
            for (int i = 0; i < 8; i++)
#pragma unroll
                for (int j = 0; j < 8; j++)
                    acc[i][j] += am[i] * bn[j];
        }
        __syncthreads();
    }
#pragma unroll
    for (int i = 0; i < 8; i++) {
        int gr = rowBase + ty * 8 + i;
        if (gr < NN) {
            __half2 p0 = __floats2half2_rn(acc[i][0], acc[i][1]);
            __half2 p1 = __floats2half2_rn(acc[i][2], acc[i][3]);
            __half2 p2 = __floats2half2_rn(acc[i][4], acc[i][5]);
            __half2 p3 = __floats2half2_rn(acc[i][6], acc[i][7]);
            uint4 u;
            u.x = *(unsigned*)&p0; u.y = *(unsigned*)&p1;
            u.z = *(unsigned*)&p2; u.w = *(unsigned*)&p3;
            *(uint4*)&g_H16[(size_t)gr * D1 + colBase + tx * 8] = u;
        }
    }
}

// ------------- GEMM2 (fp16 A-rows) + fused st40 (s,t for output layer) --------
__global__ void gemm2_kernel(const float* __restrict__ Wout,
                             const float* __restrict__ a_so,
                             const float* __restrict__ a_do) {
    __shared__ float Bs[D1 * NCLS];
    __shared__ float As_[NCLS], Ad_[NCLS];
    int tid = threadIdx.x;
    for (int i = tid; i < D1 * NCLS; i += 256) Bs[i] = Wout[i];
    if (tid < NCLS) { As_[tid] = a_so[tid]; Ad_[tid] = a_do[tid]; }
    __syncthreads();
    int row = blockIdx.x * 256 + tid;
    if (row >= NN) return;
    const __half2* arow = (const __half2*)(g_H16 + (size_t)row * D1);
    float acc[NCLS] = {};
#pragma unroll 2
    for (int k2 = 0; k2 < D1 / 2; k2++) {
        float2 a2 = __half22float2(__ldg(arow + k2));
        const float* b0 = &Bs[(2 * k2) * NCLS];
        const float* b1 = &Bs[(2 * k2 + 1) * NCLS];
#pragma unroll
        for (int c = 0; c < NCLS; c++) acc[c] += a2.x * b0[c] + a2.y * b1[c];
    }
    float* orow = g_O0 + (size_t)row * NCLS;
    float s = 0.f, t = 0.f;
#pragma unroll
    for (int c = 0; c < NCLS; c++) {
        orow[c] = acc[c];
        s += acc[c] * As_[c];
        t += acc[c] * Ad_[c];
    }
    g_S8[row] = s;     // stride-1 reuse for output layer
    g_T8[row] = t;
}

// --------------------- attention s,t for ALL 8 heads at once ------------------
__global__ void st8_kernel(const float* __restrict__ a_src,
                           const float* __restrict__ a_dst) {
    int gw = blockIdx.x * 8 + (threadIdx.x >> 5);
    int lane = threadIdx.x & 31;
    if (gw >= NN) return;
    const __half* row = g_H16 + (size_t)gw * D1;
#pragma unroll
    for (int h = 0; h < HEADS; h++) {
        float v = __half2float(row[h * HID + lane]);
        float s = warp_sum(v * a_src[h * HID + lane]);
        float t = warp_sum(v * a_dst[h * HID + lane]);
        if (lane == 0) { g_S8[(size_t)gw * 8 + h] = s; g_T8[(size_t)gw * 8 + h] = t; }
    }
}

// ------------ 8-head fused attention weights (unnormalized) + INV --------------
__global__ void attn8_kernel() {
    int d = blockIdx.x * 8 + (threadIdx.x >> 5);
    int lane = threadIdx.x & 31;
    if (d >= NN) return;
    int start = g_ROWPTR[d], end = g_ROWPTR[d + 1];
    if (start == end) {
        if (lane == 0) {
            float4 z = make_float4(0.f, 0.f, 0.f, 0.f);
            *(float4*)&g_INV8[(size_t)d * 8] = z;
            *(float4*)&g_INV8[(size_t)d * 8 + 4] = z;
        }
        return;
    }
    float4 ta = *(const float4*)&g_T8[(size_t)d * 8];
    float4 tb = *(const float4*)&g_T8[(size_t)d * 8 + 4];
    float t[8] = {ta.x, ta.y, ta.z, ta.w, tb.x, tb.y, tb.z, tb.w};
    float m[8];
#pragma unroll
    for (int i = 0; i < 8; i++) m[i] = -INFINITY;
    for (int e = start + lane; e < end; e += 32) {
        int s = g_SSRC[e];
        float4 sa = *(const float4*)&g_S8[(size_t)s * 8];
        float4 sb = *(const float4*)&g_S8[(size_t)s * 8 + 4];
        float sv[8] = {sa.x, sa.y, sa.z, sa.w, sb.x, sb.y, sb.z, sb.w};
#pragma unroll
        for (int i = 0; i < 8; i++) {
            float ev = sv[i] + t[i];
            ev = (ev >= 0.f) ? ev : LRA * ev;
            m[i] = fmaxf(m[i], ev);
        }
    }
#pragma unroll
    for (int i = 0; i < 8; i++) m[i] = warp_max(m[i]);
    float u[8] = {};
    for (int e = start + lane; e < end; e += 32) {
        int s = g_SSRC[e];
        float4 sa = *(const float4*)&g_S8[(size_t)s * 8];
        float4 sb = *(const float4*)&g_S8[(size_t)s * 8 + 4];
        float sv[8] = {sa.x, sa.y, sa.z, sa.w, sb.x, sb.y, sb.z, sb.w};
        float p[8];
#pragma unroll
        for (int i = 0; i < 8; i++) {
            float ev = sv[i] + t[i];
            ev = (ev >= 0.f) ? ev : LRA * ev;
            p[i] = expf(ev - m[i]);
            u[i] += p[i];
        }
        *(float4*)&g_WBUF[0][(size_t)e * 4] = make_float4(p[0], p[1], p[2], p[3]);
        *(float4*)&g_WBUF[1][(size_t)e * 4] = make_float4(p[4], p[5], p[6], p[7]);
    }
#pragma unroll
    for (int i = 0; i < 8; i++) u[i] = warp_sum(u[i]);
    if (lane == 0) {
        *(float4*)&g_INV8[(size_t)d * 8] =
            make_float4(1.f / (u[0] + 1e-16f), 1.f / (u[1] + 1e-16f),
                        1.f / (u[2] + 1e-16f), 1.f / (u[3] + 1e-16f));
        *(float4*)&g_INV8[(size_t)d * 8 + 4] =
            make_float4(1.f / (u[4] + 1e-16f), 1.f / (u[5] + 1e-16f),
                        1.f / (u[6] + 1e-16f), 1.f / (u[7] + 1e-16f));
    }
}

// --------- 4-head fused diffusion hop, fp16 gathers (warp per dst) ------------
// lane covers cols [g*128 + lane*4 ..+4); head within group h = lane>>3.
// mode 0: gather H16 group slice -> FA16.
// mode 1: gather FA16 -> elu -> H16 group slice in place (final H for gemm2).
__global__ void hop4_kernel(int g, int mode) {
    int d = blockIdx.x * 8 + (threadIdx.x >> 5);
    int lane = threadIdx.x & 31;
    if (d >= NN) return;
    int h = lane >> 3;
    int start = g_ROWPTR[d], end = g_ROWPTR[d + 1];
    const float* wb = g_WBUF[g];
    float4 acc = make_float4(0.f, 0.f, 0.f, 0.f);
    int e = start;
    for (; e + 4 <= end; e += 4) {
        int s0 = g_SSRC[e], s1 = g_SSRC[e + 1], s2 = g_SSRC[e + 2], s3 = g_SSRC[e + 3];
        float4 w0 = *(const float4*)&wb[(size_t)e * 4];
        float4 w1 = *(const float4*)&wb[(size_t)(e + 1) * 4];
        float4 w2 = *(const float4*)&wb[(size_t)(e + 2) * 4];
        float4 w3 = *(const float4*)&wb[(size_t)(e + 3) * 4];
        const __half *r0, *r1, *r2, *r3;
        if (mode == 0) {
            r0 = g_H16 + (size_t)s0 * D1 + g * 128;
            r1 = g_H16 + (size_t)s1 * D1 + g * 128;
            r2 = g_H16 + (size_t)s2 * D1 + g * 128;
            r3 = g_H16 + (size_t)s3 * D1 + g * 128;
        } else {
            r0 = g_FA16 + (size_t)s0 * 128;
            r1 = g_FA16 + (size_t)s1 * 128;
            r2 = g_FA16 + (size_t)s2 * 128;
            r3 = g_FA16 + (size_t)s3 * 128;
        }
        float4 v0 = ld4h(r0, lane), v1 = ld4h(r1, lane);
        float4 v2 = ld4h(r2, lane), v3 = ld4h(r3, lane);
        float wv0 = sel4(w0, h), wv1 = sel4(w1, h), wv2 = sel4(w2, h), wv3 = sel4(w3, h);
        acc.x += wv0 * v0.x + wv1 * v1.x + wv2 * v2.x + wv3 * v3.x;
        acc.y += wv0 * v0.y + wv1 * v1.y + wv2 * v2.y + wv3 * v3.y;
        acc.z += wv0 * v0.z + wv1 * v1.z + wv2 * v2.z + wv3 * v3.z;
        acc.w += wv0 * v0.w + wv1 * v1.w + wv2 * v2.w + wv3 * v3.w;
    }
    for (; e < end; e++) {
        int s0 = g_SSRC[e];
        float4 w0 = *(const float4*)&wb[(size_t)e * 4];
        const __half* r0 = (mode == 0)
            ? g_H16 + (size_t)s0 * D1 + g * 128
            : g_FA16 + (size_t)s0 * 128;
        float4 v0 = ld4h(r0, lane);
        float wv0 = sel4(w0, h);
        acc.x += wv0 * v0.x; acc.y += wv0 * v0.y;
        acc.z += wv0 * v0.z; acc.w += wv0 * v0.w;
    }
    float4 inv4 = *(const float4*)&g_INV8[(size_t)d * 8 + g * 4];
    float invv = sel4(inv4, h);
    __half* h0p = g_H16 + (size_t)d * D1 + g * 128;
    float4 h0v = ld4h(h0p, lane);        // teleport term (fp16-rounded h0)
    float4 v;
    v.x = ONE_MB * acc.x * invv + BETA * h0v.x;
    v.y = ONE_MB * acc.y * invv + BETA * h0v.y;
    v.z = ONE_MB * acc.z * invv + BETA * h0v.z;
    v.w = ONE_MB * acc.w * invv + BETA * h0v.w;
    if (mode == 0) {
        st4h(g_FA16 + (size_t)d * 128, lane, v);
    } else {
        v.x = (v.x > 0.f) ? v.x : expm1f(v.x);
        v.y = (v.y > 0.f) ? v.y : expm1f(v.y);
        v.z = (v.z > 0.f) ? v.z : expm1f(v.z);
        v.w = (v.w > 0.f) ? v.w : expm1f(v.w);
        st4h(h0p, lane, v);              // final H (fp16) in place
    }
}

// ------------------------------ output layer -----------------------------------
__global__ void attn_w_kernel() {      // normalized weights into g_WBUF[0]
    int d = blockIdx.x * 8 + (threadIdx.x >> 5);
    int lane = threadIdx.x & 31;
    if (d >= NN) return;
    int start = g_ROWPTR[d], end = g_ROWPTR[d + 1];
    if (start == end) return;
    float* wb = g_WBUF[0];
    float td = g_T8[d];
    float m = -INFINITY;
    for (int e = start + lane; e < end; e += 32) {
        float ev = g_S8[g_SSRC[e]] + td;
        ev = (ev >= 0.f) ? ev : LRA * ev;
        m = fmaxf(m, ev);
    }
    m = warp_max(m);
    float sum = 0.f;
    for (int e = start + lane; e < end; e += 32) {
        float ev = g_S8[g_SSRC[e]] + td;
        ev = (ev >= 0.f) ? ev : LRA * ev;
        float p = expf(ev - m);
        wb[e] = p;
        sum += p;
    }
    sum = warp_sum(sum);
    float inv = 1.f / (sum + 1e-16f);
    for (int e = start + lane; e < end; e += 32) wb[e] *= inv;
}

__global__ void hop40_kernel(int mode, float* __restrict__ out) {
    int d = blockIdx.x * 8 + (threadIdx.x >> 5);
    int lane = threadIdx.x & 31;
    if (d >= NN) return;
    int start = g_ROWPTR[d], end = g_ROWPTR[d + 1];
    float acca = 0.f, accb = 0.f;
    bool hi = (lane < 8);
    const float* base = (mode == 0) ? g_O0 : g_GA;
    const float* wb = g_WBUF[0];
    int e = start;
    for (; e + 4 <= end; e += 4) {
        int s0 = g_SSRC[e], s1 = g_SSRC[e + 1], s2 = g_SSRC[e + 2], s3 = g_SSRC[e + 3];
        float w0 = wb[e], w1 = wb[e + 1], w2 = wb[e + 2], w3 = wb[e + 3];
        const float* r0 = base + (size_t)s0 * NCLS;
        const float* r1 = base + (size_t)s1 * NCLS;
        const float* r2 = base + (size_t)s2 * NCLS;
        const float* r3 = base + (size_t)s3 * NCLS;
        acca += w0 * r0[lane] + w1 * r1[lane] + w2 * r2[lane] + w3 * r3[lane];
        if (hi)
            accb += w0 * r0[32 + lane] + w1 * r1[32 + lane]
                  + w2 * r2[32 + lane] + w3 * r3[32 + lane];
    }
    for (; e < end; e++) {
        int s = g_SSRC[e];
        float w = wb[e];
        const float* row = base + (size_t)s * NCLS;
        acca += w * row[lane];
        if (hi) accb += w * row[32 + lane];
    }
    const float* h0row = g_O0 + (size_t)d * NCLS;
    float va = ONE_MB * acca + BETA * h0row[lane];
    float vb = hi ? (ONE_MB * accb + BETA * h0row[32 + lane]) : 0.f;
    if (mode == 0) {
        float* orow = g_GA + (size_t)d * NCLS;
        orow[lane] = va;
        if (hi) orow[32 + lane] = vb;
    } else {
        float ea = (va > 0.f) ? va : expm1f(va);
        float eb = hi ? ((vb > 0.f) ? vb : expm1f(vb)) : -INFINITY;
        float mx = warp_max(fmaxf(ea, eb));
        float se = expf(ea - mx) + (hi ? expf(eb - mx) : 0.f);
        se = warp_sum(se);
        float lse = mx + logf(se);
        float* orow = out + (size_t)d * NCLS;
        orow[lane] = ea - lse;
        if (hi) orow[32 + lane] = eb - lse;
    }
}

// --------------------------------- launch -------------------------------------
extern "C" void kernel_launch(void* const* d_in, const int* in_sizes, int n_in,
                              void* d_out, int out_size) {
    const float* x     = (const float*)d_in[0];
    const void*  ei    = d_in[1];
    const float* W     = (const float*)d_in[2];
    const float* a_src = (const float*)d_in[3];
    const float* a_dst = (const float*)d_in[4];
    const float* Wout  = (const float*)d_in[5];
    const float* a_so  = (const float*)d_in[6];
    const float* a_do  = (const float*)d_in[7];
    float*       out   = (float*)d_out;

    const int NWARP_GRID = (NN + 7) / 8;
    const int EGRID = (EE + 255) / 256;
    const int NGRID = (NN + 255) / 256;

    sniff_kernel<<<1, 256>>>((const int*)ei);
    zero_counts_kernel<<<NGRID, 256>>>();
    build_deg_kernel<<<EGRID, 256>>>(ei);
    scanA_kernel<<<NBLK, 256>>>();
    scanB_kernel<<<1, 128>>>();
    scanC_kernel<<<NBLK, 256>>>();
    scatter_kernel<<<EGRID, 256>>>(ei);

    gemm1_kernel<<<dim3((NN + 127) / 128, D1 / 128), 256>>>(x, W);
    st8_kernel<<<NWARP_GRID, 256>>>(a_src, a_dst);
    attn8_kernel<<<NWARP_GRID, 256>>>();

    for (int g = 0; g < 2; g++) {
        hop4_kernel<<<NWARP_GRID, 256>>>(g, 0);
        hop4_kernel<<<NWARP_GRID, 256>>>(g, 1);
    }

    gemm2_kernel<<<(NN + 255) / 256, 256>>>(Wout, a_so, a_do);

    attn_w_kernel<<<NWARP_GRID, 256>>>();
    hop40_kernel<<<NWARP_GRID, 256>>>(0, nullptr);
    hop40_kernel<<<NWARP_GRID, 256>>>(1, out);
}

// round 14
// speedup vs baseline: 1.1295x; 1.0521x over previous
#include <cuda_runtime.h>
#include <cuda_fp16.h>
#include <math.h>

#define NN 100000
#define EE 1600000
#define FIN 128
#define HID 32
#define HEADS 8
#define D1 256        // HEADS*HID
#define NCLS 40
#define BETA 0.1f
#define ONE_MB 0.9f   // 1-beta
#define LRA 0.2f      // leaky relu alpha
#define SCB 1024
#define NBLK ((NN + SCB - 1) / SCB)

// ------------- scratch (device globals; total ~151 MB, < 256 MB) -------------
__device__ __align__(128) __half g_H16[(size_t)NN * D1];  // features fp16
__device__ __align__(128) __half g_FA16[(size_t)NN * 128];// hop-1 intermediate (fp16)
__device__ __align__(128) float  g_O0[(size_t)NN * NCLS]; // H @ W_out (fp32, teleport/epilogue)
__device__ __align__(128) __half g_O16[(size_t)NN * NCLS];// fp16 copy for gathers
__device__ __align__(128) __half g_GA16[(size_t)NN * NCLS];// layer-2 hop-1 (fp16)
__device__ __align__(128) __half g_W16[2][(size_t)EE * 4];// unnorm attn w (fp16, packed)
__device__ __align__(128) int    g_SSRC[EE];              // src sorted by dst (CSR)
__device__ __align__(128) float  g_S8[(size_t)NN * 8];
__device__ __align__(128) float  g_T8[(size_t)NN * 8];
__device__ __align__(128) float  g_INV8[(size_t)NN * 8];
__device__ int   g_ROWPTR[NN + 1];
__device__ int   g_DEG[NN];
__device__ int   g_CUR[NN];
__device__ int   g_BSUM[NBLK];
__device__ int   g_BOFF[NBLK];
__device__ int   g_EI64;

// ------------------------------- helpers --------------------------------------
__device__ __forceinline__ float warp_sum(float v) {
#pragma unroll
    for (int o = 16; o > 0; o >>= 1) v += __shfl_xor_sync(0xffffffffu, v, o);
    return v;
}
__device__ __forceinline__ float warp_max(float v) {
#pragma unroll
    for (int o = 16; o > 0; o >>= 1) v = fmaxf(v, __shfl_xor_sync(0xffffffffu, v, o));
    return v;
}
__device__ __forceinline__ int warp_sum_i(int v) {
#pragma unroll
    for (int o = 16; o > 0; o >>= 1) v += __shfl_xor_sync(0xffffffffu, v, o);
    return v;
}
__device__ __forceinline__ float sel4(float4 w, int h) {
    return (h == 0) ? w.x : (h == 1) ? w.y : (h == 2) ? w.z : w.w;
}
// load 4 halves (8B) -> 4 floats
__device__ __forceinline__ float4 ld4h(const __half* p, int idx4) {
    uint2 u = ((const uint2*)p)[idx4];
    float2 f0 = __half22float2(*(__half2*)&u.x);
    float2 f1 = __half22float2(*(__half2*)&u.y);
    return make_float4(f0.x, f0.y, f1.x, f1.y);
}
// store 4 floats -> 4 halves (8B)
__device__ __forceinline__ void st4h(__half* p, int idx4, float4 v) {
    __half2 pa = __floats2half2_rn(v.x, v.y);
    __half2 pb = __floats2half2_rn(v.z, v.w);
    uint2 u;
    u.x = *(unsigned*)&pa;
    u.y = *(unsigned*)&pb;
    ((uint2*)p)[idx4] = u;
}

// ------------------------- edge dtype sniff (parallel) -------------------------
__global__ void sniff_kernel(const int* __restrict__ ei32) {
    int bad = 0;
    for (int i = threadIdx.x; i < 512; i += 256)
        bad |= (ei32[2 * i + 1] != 0);
    bad = __syncthreads_or(bad);
    if (threadIdx.x == 0) g_EI64 = bad ? 0 : 1;
}

__device__ __forceinline__ int load_node(const void* ei, size_t pos, int is64) {
    if (is64) return (int)((const long long*)ei)[pos];
    return ((const int*)ei)[pos];
}

// ------------------------------ CSR build -------------------------------------
__global__ void zero_counts_kernel() {
    int i = blockIdx.x * blockDim.x + threadIdx.x;
    if (i < NN) { g_DEG[i] = 0; g_CUR[i] = 0; }
}

__global__ void build_deg_kernel(const void* __restrict__ ei) {
    int e = blockIdx.x * blockDim.x + threadIdx.x;
    if (e >= EE) return;
    int d = load_node(ei, (size_t)EE + e, g_EI64);
    if ((unsigned)d < NN) atomicAdd(&g_DEG[d], 1);
}

__global__ void scanA_kernel() {
    __shared__ int wsum[8];
    int tid = threadIdx.x;
    int base = blockIdx.x * SCB + tid * 4;
    int s = 0;
#pragma unroll
    for (int j = 0; j < 4; j++) { int i = base + j; if (i < NN) s += g_DEG[i]; }
    s = warp_sum_i(s);
    if ((tid & 31) == 0) wsum[tid >> 5] = s;
    __syncthreads();
    if (tid == 0) {
        int t = 0;
#pragma unroll
        for (int w = 0; w < 8; w++) t += wsum[w];
        g_BSUM[blockIdx.x] = t;
    }
}

__global__ void scanB_kernel() {
    __shared__ int sm[4];
    int tid = threadIdx.x, lane = tid & 31, wid = tid >> 5;
    int v = (tid < NBLK) ? g_BSUM[tid] : 0;
    int x = v;
#pragma unroll
    for (int o = 1; o < 32; o <<= 1) {
        int y = __shfl_up_sync(0xffffffffu, x, o);
        if (lane >= o) x += y;
    }
    if (lane == 31) sm[wid] = x;
    __syncthreads();
    int woff = 0;
    for (int w = 0; w < wid; w++) woff += sm[w];
    if (tid < NBLK) g_BOFF[tid] = woff + x - v;
}

__global__ void scanC_kernel() {
    __shared__ int wsum[8];
    int tid = threadIdx.x, lane = tid & 31, wid = tid >> 5;
    int base = blockIdx.x * SCB + tid * 4;
    int a0 = (base + 0 < NN) ? g_DEG[base + 0] : 0;
    int a1 = (base + 1 < NN) ? g_DEG[base + 1] : 0;
    int a2 = (base + 2 < NN) ? g_DEG[base + 2] : 0;
    int a3 = (base + 3 < NN) ? g_DEG[base + 3] : 0;
    int tsum = a0 + a1 + a2 + a3;
    int x = tsum;
#pragma unroll
    for (int o = 1; o < 32; o <<= 1) {
        int y = __shfl_up_sync(0xffffffffu, x, o);
        if (lane >= o) x += y;
    }
    if (lane == 31) wsum[wid] = x;
    __syncthreads();
    int woff = 0;
    for (int w = 0; w < wid; w++) woff += wsum[w];
    int excl = g_BOFF[blockIdx.x] + woff + (x - tsum);
    if (base + 0 < NN) g_ROWPTR[base + 1] = excl + a0;
    if (base + 1 < NN) g_ROWPTR[base + 2] = excl + a0 + a1;
    if (base + 2 < NN) g_ROWPTR[base + 3] = excl + a0 + a1 + a2;
    if (base + 3 < NN) g_ROWPTR[base + 4] = excl + tsum;
    if (blockIdx.x == 0 && tid == 0) g_ROWPTR[0] = 0;
}

__global__ void scatter_kernel(const void* __restrict__ ei) {
    int e = blockIdx.x * blockDim.x + threadIdx.x;
    if (e >= EE) return;
    int is64 = g_EI64;
    int s = load_node(ei, (size_t)e, is64);
    int d = load_node(ei, (size_t)EE + e, is64);
    if ((unsigned)d >= NN || (unsigned)s >= NN) return;
    int pos = g_ROWPTR[d] + atomicAdd(&g_CUR[d], 1);
    if ((unsigned)pos < EE) g_SSRC[pos] = s;
}

// ------------- GEMM1: 128x128 block, 8x8/thread -> fp16 feature table ---------
__global__ void __launch_bounds__(256) gemm1_kernel(const float* __restrict__ x,
                                                    const float* __restrict__ W) {
    __shared__ float As[16][132];
    __shared__ float Bs[16][132];
    int tid = threadIdx.x;
    int tx = tid & 15;
    int ty = tid >> 4;
    int rowBase = blockIdx.x * 128;
    int colBase = blockIdx.y * 128;
    float acc[8][8] = {};
    for (int kt = 0; kt < FIN; kt += 16) {
#pragma unroll
        for (int p = 0; p < 2; p++) {
            int idx = tid + p * 256;
            int r = idx & 127;
            int kq = idx >> 7;
            int gr = rowBase + r;
            float4 v = make_float4(0.f, 0.f, 0.f, 0.f);
            if (gr < NN) v = *(const float4*)&x[(size_t)gr * FIN + kt + kq * 4];
            As[kq * 4 + 0][r] = v.x;
            As[kq * 4 + 1][r] = v.y;
            As[kq * 4 + 2][r] = v.z;
            As[kq * 4 + 3][r] = v.w;
        }
#pragma unroll
        for (int p = 0; p < 2; p++) {
            int idx = tid + p * 256;
            int k = idx >> 5;
            int q = idx & 31;
            int col = colBase + q * 4;
            float4 v = *(const float4*)&W[(size_t)(col >> 5) * (FIN * HID)
                                          + (size_t)(kt + k) * HID + (col & 31)];
            *(float4*)&Bs[k][q * 4] = v;
        }
        __syncthreads();
#pragma unroll
        for (int k = 0; k < 16; k++) {
            float4 a0 = *(const float4*)&As[k][ty * 8];
            float4 a1 = *(const float4*)&As[k][ty * 8 + 4];
            float4 b0 = *(const float4*)&Bs[k][tx * 8];
            float4 b1 = *(const float4*)&Bs[k][tx * 8 + 4];
            float am[8] = {a0.x, a0.y, a0.z, a0.w, a1.x, a1.y, a1.z, a1.w};
            float bn[8] = {b0.x, b0.y, b0.z, b0.w, b1.x, b1.y, b1.z, b1.w};
#pragma unroll
            for (int i = 0; i < 8; i++)
#pragma unroll
                for (int j = 0; j < 8; j++)
                    acc[i][j] += am[i] * bn[j];
        }
        __syncthreads();
    }
#pragma unroll
    for (int i = 0; i < 8; i++) {
        int gr = rowBase + ty * 8 + i;
        if (gr < NN) {
            __half2 p0 = __floats2half2_rn(acc[i][0], acc[i][1]);
            __half2 p1 = __floats2half2_rn(acc[i][2], acc[i][3]);
            __half2 p2 = __floats2half2_rn(acc[i][4], acc[i][5]);
            __half2 p3 = __floats2half2_rn(acc[i][6], acc[i][7]);
            uint4 u;
            u.x = *(unsigned*)&p0; u.y = *(unsigned*)&p1;
            u.z = *(unsigned*)&p2; u.w = *(unsigned*)&p3;
            *(uint4*)&g_H16[(size_t)gr * D1 + colBase + tx * 8] = u;
        }
    }
}

// ---- GEMM2 (fp16 A-rows) + fused st40; writes O0 (fp32) and O16 (fp16) -------
__global__ void gemm2_kernel(const float* __restrict__ Wout,
                             const float* __restrict__ a_so,
                             const float* __restrict__ a_do) {
    __shared__ float Bs[D1 * NCLS];
    __shared__ float As_[NCLS], Ad_[NCLS];
    int tid = threadIdx.x;
    for (int i = tid; i < D1 * NCLS; i += 256) Bs[i] = Wout[i];
    if (tid < NCLS) { As_[tid] = a_so[tid]; Ad_[tid] = a_do[tid]; }
    __syncthreads();
    int row = blockIdx.x * 256 + tid;
    if (row >= NN) return;
    const __half2* arow = (const __half2*)(g_H16 + (size_t)row * D1);
    float acc[NCLS] = {};
#pragma unroll 2
    for (int k2 = 0; k2 < D1 / 2; k2++) {
        float2 a2 = __half22float2(__ldg(arow + k2));
        const float* b0 = &Bs[(2 * k2) * NCLS];
        const float* b1 = &Bs[(2 * k2 + 1) * NCLS];
#pragma unroll
        for (int c = 0; c < NCLS; c++) acc[c] += a2.x * b0[c] + a2.y * b1[c];
    }
    float* orow = g_O0 + (size_t)row * NCLS;
    __half* orow16 = g_O16 + (size_t)row * NCLS;
    float s = 0.f, t = 0.f;
#pragma unroll
    for (int c = 0; c < NCLS; c++) {
        orow[c] = acc[c];
        orow16[c] = __float2half_rn(acc[c]);
        s += acc[c] * As_[c];
        t += acc[c] * Ad_[c];
    }
    g_S8[row] = s;     // stride-1 reuse for output layer
    g_T8[row] = t;
}

// --------------------- attention s,t for ALL 8 heads at once ------------------
__global__ void st8_kernel(const float* __restrict__ a_src,
                           const float* __restrict__ a_dst) {
    int gw = blockIdx.x * 8 + (threadIdx.x >> 5);
    int lane = threadIdx.x & 31;
    if (gw >= NN) return;
    const __half* row = g_H16 + (size_t)gw * D1;
#pragma unroll
    for (int h = 0; h < HEADS; h++) {
        float v = __half2float(row[h * HID + lane]);
        float s = warp_sum(v * a_src[h * HID + lane]);
        float t = warp_sum(v * a_dst[h * HID + lane]);
        if (lane == 0) { g_S8[(size_t)gw * 8 + h] = s; g_T8[(size_t)gw * 8 + h] = t; }
    }
}

// ----- 8-head fused attention weights (unnormalized, fp16-stored) + INV --------
__global__ void attn8_kernel() {
    int d = blockIdx.x * 8 + (threadIdx.x >> 5);
    int lane = threadIdx.x & 31;
    if (d >= NN) return;
    int start = g_ROWPTR[d], end = g_ROWPTR[d + 1];
    if (start == end) {
        if (lane == 0) {
            float4 z = make_float4(0.f, 0.f, 0.f, 0.f);
            *(float4*)&g_INV8[(size_t)d * 8] = z;
            *(float4*)&g_INV8[(size_t)d * 8 + 4] = z;
        }
        return;
    }
    float4 ta = *(const float4*)&g_T8[(size_t)d * 8];
    float4 tb = *(const float4*)&g_T8[(size_t)d * 8 + 4];
    float t[8] = {ta.x, ta.y, ta.z, ta.w, tb.x, tb.y, tb.z, tb.w};
    float m[8];
#pragma unroll
    for (int i = 0; i < 8; i++) m[i] = -INFINITY;
    for (int e = start + lane; e < end; e += 32) {
        int s = g_SSRC[e];
        float4 sa = *(const float4*)&g_S8[(size_t)s * 8];
        float4 sb = *(const float4*)&g_S8[(size_t)s * 8 + 4];
        float sv[8] = {sa.x, sa.y, sa.z, sa.w, sb.x, sb.y, sb.z, sb.w};
#pragma unroll
        for (int i = 0; i < 8; i++) {
            float ev = sv[i] + t[i];
            ev = (ev >= 0.f) ? ev : LRA * ev;
            m[i] = fmaxf(m[i], ev);
        }
    }
#pragma unroll
    for (int i = 0; i < 8; i++) m[i] = warp_max(m[i]);
    float u[8] = {};
    for (int e = start + lane; e < end; e += 32) {
        int s = g_SSRC[e];
        float4 sa = *(const float4*)&g_S8[(size_t)s * 8];
        float4 sb = *(const float4*)&g_S8[(size_t)s * 8 + 4];
        float sv[8] = {sa.x, sa.y, sa.z, sa.w, sb.x, sb.y, sb.z, sb.w};
        float p[8];
#pragma unroll
        for (int i = 0; i < 8; i++) {
            float ev = sv[i] + t[i];
            ev = (ev >= 0.f) ? ev : LRA * ev;
            p[i] = expf(ev - m[i]);
            u[i] += p[i];
        }
        st4h(g_W16[0], e, make_float4(p[0], p[1], p[2], p[3]));
        st4h(g_W16[1], e, make_float4(p[4], p[5], p[6], p[7]));
    }
#pragma unroll
    for (int i = 0; i < 8; i++) u[i] = warp_sum(u[i]);
    if (lane == 0) {
        *(float4*)&g_INV8[(size_t)d * 8] =
            make_float4(1.f / (u[0] + 1e-16f), 1.f / (u[1] + 1e-16f),
                        1.f / (u[2] + 1e-16f), 1.f / (u[3] + 1e-16f));
        *(float4*)&g_INV8[(size_t)d * 8 + 4] =
            make_float4(1.f / (u[4] + 1e-16f), 1.f / (u[5] + 1e-16f),
                        1.f / (u[6] + 1e-16f), 1.f / (u[7] + 1e-16f));
    }
}

// --------- 4-head fused diffusion hop, fp16 gathers + fp16 weights ------------
__global__ void hop4_kernel(int g, int mode) {
    int d = blockIdx.x * 8 + (threadIdx.x >> 5);
    int lane = threadIdx.x & 31;
    if (d >= NN) return;
    int h = lane >> 3;
    int start = g_ROWPTR[d], end = g_ROWPTR[d + 1];
    const __half* wb = g_W16[g];
    float4 acc = make_float4(0.f, 0.f, 0.f, 0.f);
    int e = start;
    for (; e + 4 <= end; e += 4) {
        int s0 = g_SSRC[e], s1 = g_SSRC[e + 1], s2 = g_SSRC[e + 2], s3 = g_SSRC[e + 3];
        float4 w0 = ld4h(wb, e);
        float4 w1 = ld4h(wb, e + 1);
        float4 w2 = ld4h(wb, e + 2);
        float4 w3 = ld4h(wb, e + 3);
        const __half *r0, *r1, *r2, *r3;
        if (mode == 0) {
            r0 = g_H16 + (size_t)s0 * D1 + g * 128;
            r1 = g_H16 + (size_t)s1 * D1 + g * 128;
            r2 = g_H16 + (size_t)s2 * D1 + g * 128;
            r3 = g_H16 + (size_t)s3 * D1 + g * 128;
        } else {
            r0 = g_FA16 + (size_t)s0 * 128;
            r1 = g_FA16 + (size_t)s1 * 128;
            r2 = g_FA16 + (size_t)s2 * 128;
            r3 = g_FA16 + (size_t)s3 * 128;
        }
        float4 v0 = ld4h(r0, lane), v1 = ld4h(r1, lane);
        float4 v2 = ld4h(r2, lane), v3 = ld4h(r3, lane);
        float wv0 = sel4(w0, h), wv1 = sel4(w1, h), wv2 = sel4(w2, h), wv3 = sel4(w3, h);
        acc.x += wv0 * v0.x + wv1 * v1.x + wv2 * v2.x + wv3 * v3.x;
        acc.y += wv0 * v0.y + wv1 * v1.y + wv2 * v2.y + wv3 * v3.y;
        acc.z += wv0 * v0.z + wv1 * v1.z + wv2 * v2.z + wv3 * v3.z;
        acc.w += wv0 * v0.w + wv1 * v1.w + wv2 * v2.w + wv3 * v3.w;
    }
    for (; e < end; e++) {
        int s0 = g_SSRC[e];
        float4 w0 = ld4h(wb, e);
        const __half* r0 = (mode == 0)
            ? g_H16 + (size_t)s0 * D1 + g * 128
            : g_FA16 + (size_t)s0 * 128;
        float4 v0 = ld4h(r0, lane);
        float wv0 = sel4(w0, h);
        acc.x += wv0 * v0.x; acc.y += wv0 * v0.y;
        acc.z += wv0 * v0.z; acc.w += wv0 * v0.w;
    }
    float4 inv4 = *(const float4*)&g_INV8[(size_t)d * 8 + g * 4];
    float invv = sel4(inv4, h);
    __half* h0p = g_H16 + (size_t)d * D1 + g * 128;
    float4 h0v = ld4h(h0p, lane);
    float4 v;
    v.x = ONE_MB * acc.x * invv + BETA * h0v.x;
    v.y = ONE_MB * acc.y * invv + BETA * h0v.y;
    v.z = ONE_MB * acc.z * invv + BETA * h0v.z;
    v.w = ONE_MB * acc.w * invv + BETA * h0v.w;
    if (mode == 0) {
        st4h(g_FA16 + (size_t)d * 128, lane, v);
    } else {
        v.x = (v.x > 0.f) ? v.x : expm1f(v.x);
        v.y = (v.y > 0.f) ? v.y : expm1f(v.y);
        v.z = (v.z > 0.f) ? v.z : expm1f(v.z);
        v.w = (v.w > 0.f) ? v.w : expm1f(v.w);
        st4h(h0p, lane, v);
    }
}

// ------------------------------ output layer -----------------------------------
__global__ void attn_w_kernel() {      // normalized weights into g_W16[0] (fp16)
    int d = blockIdx.x * 8 + (threadIdx.x >> 5);
    int lane = threadIdx.x & 31;
    if (d >= NN) return;
    int start = g_ROWPTR[d], end = g_ROWPTR[d + 1];
    if (start == end) return;
    __half* wb = g_W16[0];
    float td = g_T8[d];
    float m = -INFINITY;
    for (int e = start + lane; e < end; e += 32) {
        float ev = g_S8[g_SSRC[e]] + td;
        ev = (ev >= 0.f) ? ev : LRA * ev;
        m = fmaxf(m, ev);
    }
    m = warp_max(m);
    float sum = 0.f;
    for (int e = start + lane; e < end; e += 32) {
        float ev = g_S8[g_SSRC[e]] + td;
        ev = (ev >= 0.f) ? ev : LRA * ev;
        sum += expf(ev - m);
    }
    sum = warp_sum(sum);
    float inv = 1.f / (sum + 1e-16f);
    for (int e = start + lane; e < end; e += 32) {
        float ev = g_S8[g_SSRC[e]] + td;
        ev = (ev >= 0.f) ? ev : LRA * ev;
        wb[e] = __float2half_rn(expf(ev - m) * inv);
    }
}

__global__ void hop40_kernel(int mode, float* __restrict__ out) {
    int d = blockIdx.x * 8 + (threadIdx.x >> 5);
    int lane = threadIdx.x & 31;
    if (d >= NN) return;
    int start = g_ROWPTR[d], end = g_ROWPTR[d + 1];
    float acca = 0.f, accb = 0.f;
    bool hi = (lane < 8);
    const __half* base = (mode == 0) ? g_O16 : g_GA16;
    const __half* wb = g_W16[0];
    int e = start;
    for (; e + 4 <= end; e += 4) {
        int s0 = g_SSRC[e], s1 = g_SSRC[e + 1], s2 = g_SSRC[e + 2], s3 = g_SSRC[e + 3];
        float w0 = __half2float(wb[e]);
        float w1 = __half2float(wb[e + 1]);
        float w2 = __half2float(wb[e + 2]);
        float w3 = __half2float(wb[e + 3]);
        const __half* r0 = base + (size_t)s0 * NCLS;
        const __half* r1 = base + (size_t)s1 * NCLS;
        const __half* r2 = base + (size_t)s2 * NCLS;
        const __half* r3 = base + (size_t)s3 * NCLS;
        acca += w0 * __half2float(r0[lane]) + w1 * __half2float(r1[lane])
              + w2 * __half2float(r2[lane]) + w3 * __half2float(r3[lane]);
        if (hi)
            accb += w0 * __half2float(r0[32 + lane]) + w1 * __half2float(r1[32 + lane])
                  + w2 * __half2float(r2[32 + lane]) + w3 * __half2float(r3[32 + lane]);
    }
    for (; e < end; e++) {
        int s = g_SSRC[e];
        float w = __half2float(wb[e]);
        const __half* row = base + (size_t)s * NCLS;
        acca += w * __half2float(row[lane]);
        if (hi) accb += w * __half2float(row[32 + lane]);
    }
    const float* h0row = g_O0 + (size_t)d * NCLS;   // exact fp32 teleport
    float va = ONE_MB * acca + BETA * h0row[lane];
    float vb = hi ? (ONE_MB * accb + BETA * h0row[32 + lane]) : 0.f;
    if (mode == 0) {
        __half* orow = g_GA16 + (size_t)d * NCLS;
        orow[lane] = __float2half_rn(va);
        if (hi) orow[32 + lane] = __float2half_rn(vb);
    } else {
        float ea = (va > 0.f) ? va : expm1f(va);
        float eb = hi ? ((vb > 0.f) ? vb : expm1f(vb)) : -INFINITY;
        float mx = warp_max(fmaxf(ea, eb));
        float se = expf(ea - mx) + (hi ? expf(eb - mx) : 0.f);
        se = warp_sum(se);
        float lse = mx + logf(se);
        float* orow = out + (size_t)d * NCLS;
        orow[lane] = ea - lse;
        if (hi) orow[32 + lane] = eb - lse;
    }
}

// --------------------------------- launch -------------------------------------
extern "C" void kernel_launch(void* const* d_in, const int* in_sizes, int n_in,
                              void* d_out, int out_size) {
    const float* x     = (const float*)d_in[0];
    const void*  ei    = d_in[1];
    const float* W     = (const float*)d_in[2];
    const float* a_src = (const float*)d_in[3];
    const float* a_dst = (const float*)d_in[4];
    const float* Wout  = (const float*)d_in[5];
    const float* a_so  = (const float*)d_in[6];
    const float* a_do  = (const float*)d_in[7];
    float*       out   = (float*)d_out;

    const int NWARP_GRID = (NN + 7) / 8;
    const int EGRID = (EE + 255) / 256;
    const int NGRID = (NN + 255) / 256;

    sniff_kernel<<<1, 256>>>((const int*)ei);
    zero_counts_kernel<<<NGRID, 256>>>();
    build_deg_kernel<<<EGRID, 256>>>(ei);
    scanA_kernel<<<NBLK, 256>>>();
    scanB_kernel<<<1, 128>>>();
    scanC_kernel<<<NBLK, 256>>>();
    scatter_kernel<<<EGRID, 256>>>(ei);

    gemm1_kernel<<<dim3((NN + 127) / 128, D1 / 128), 256>>>(x, W);
    st8_kernel<<<NWARP_GRID, 256>>>(a_src, a_dst);
    attn8_kernel<<<NWARP_GRID, 256>>>();

    for (int g = 0; g < 2; g++) {
        hop4_kernel<<<NWARP_GRID, 256>>>(g, 0);
        hop4_kernel<<<NWARP_GRID, 256>>>(g, 1);
    }

    gemm2_kernel<<<(NN + 255) / 256, 256>>>(Wout, a_so, a_do);

    attn_w_kernel<<<NWARP_GRID, 256>>>();
    hop40_kernel<<<NWARP_GRID, 256>>>(0, nullptr);
    hop40_kernel<<<NWARP_GRID, 256>>>(1, out);
}

// round 15
// speedup vs baseline: 1.2855x; 1.1381x over previous
#include <cuda_runtime.h>
#include <cuda_fp16.h>
#include <mma.h>
#include <math.h>

using namespace nvcuda;

#define NN 100000
#define EE 1600000
#define FIN 128
#define HID 32
#define HEADS 8
#define D1 256        // HEADS*HID
#define NCLS 40
#define BETA 0.1f
#define ONE_MB 0.9f   // 1-beta
#define LRA 0.2f      // leaky relu alpha
#define SCB 1024
#define NBLK ((NN + SCB - 1) / SCB)

// ------------- scratch (device globals; total ~177 MB, < 256 MB) -------------
__device__ __align__(128) __half g_H16[(size_t)NN * D1];  // features fp16
__device__ __align__(128) __half g_FA16[(size_t)NN * 128];// hop-1 intermediate (fp16)
__device__ __align__(128) __half g_X16[(size_t)NN * FIN]; // x in fp16 (for wmma)
__device__ __align__(128) __half g_W16w[FIN * D1];        // W in fp16, [k][col] row-major
__device__ __align__(128) float  g_O0[(size_t)NN * NCLS]; // H @ W_out (fp32)
__device__ __align__(128) __half g_O16[(size_t)NN * NCLS];// fp16 copy for gathers
__device__ __align__(128) __half g_GA16[(size_t)NN * NCLS];// layer-2 hop-1 (fp16)
__device__ __align__(128) __half g_W16[2][(size_t)EE * 4];// unnorm attn w (fp16, packed)
__device__ __align__(128) int    g_SSRC[EE];              // src sorted by dst (CSR)
__device__ __align__(128) float  g_S8[(size_t)NN * 8];
__device__ __align__(128) float  g_T8[(size_t)NN * 8];
__device__ __align__(128) float  g_INV8[(size_t)NN * 8];
__device__ int   g_ROWPTR[NN + 1];
__device__ int   g_DEG[NN];
__device__ int   g_CUR[NN];
__device__ int   g_BSUM[NBLK];
__device__ int   g_BOFF[NBLK];
__device__ int   g_EI64;

// ------------------------------- helpers --------------------------------------
__device__ __forceinline__ float warp_sum(float v) {
#pragma unroll
    for (int o = 16; o > 0; o >>= 1) v += __shfl_xor_sync(0xffffffffu, v, o);
    return v;
}
__device__ __forceinline__ float warp_max(float v) {
#pragma unroll
    for (int o = 16; o > 0; o >>= 1) v = fmaxf(v, __shfl_xor_sync(0xffffffffu, v, o));
    return v;
}
__device__ __forceinline__ int warp_sum_i(int v) {
#pragma unroll
    for (int o = 16; o > 0; o >>= 1) v += __shfl_xor_sync(0xffffffffu, v, o);
    return v;
}
__device__ __forceinline__ float sel4(float4 w, int h) {
    return (h == 0) ? w.x : (h == 1) ? w.y : (h == 2) ? w.z : w.w;
}
__device__ __forceinline__ float4 ld4h(const __half* p, int idx4) {
    uint2 u = ((const uint2*)p)[idx4];
    float2 f0 = __half22float2(*(__half2*)&u.x);
    float2 f1 = __half22float2(*(__half2*)&u.y);
    return make_float4(f0.x, f0.y, f1.x, f1.y);
}
__device__ __forceinline__ void st4h(__half* p, int idx4, float4 v) {
    __half2 pa = __floats2half2_rn(v.x, v.y);
    __half2 pb = __floats2half2_rn(v.z, v.w);
    uint2 u;
    u.x = *(unsigned*)&pa;
    u.y = *(unsigned*)&pb;
    ((uint2*)p)[idx4] = u;
}

// ------------------------- edge dtype sniff (parallel) -------------------------
__global__ void sniff_kernel(const int* __restrict__ ei32) {
    int bad = 0;
    for (int i = threadIdx.x; i < 512; i += 256)
        bad |= (ei32[2 * i + 1] != 0);
    bad = __syncthreads_or(bad);
    if (threadIdx.x == 0) g_EI64 = bad ? 0 : 1;
}

__device__ __forceinline__ int load_node(const void* ei, size_t pos, int is64) {
    if (is64) return (int)((const long long*)ei)[pos];
    return ((const int*)ei)[pos];
}

// ------------------------------ CSR build -------------------------------------
__global__ void zero_counts_kernel() {
    int i = blockIdx.x * blockDim.x + threadIdx.x;
    if (i < NN) { g_DEG[i] = 0; g_CUR[i] = 0; }
}

__global__ void build_deg_kernel(const void* __restrict__ ei) {
    int e = blockIdx.x * blockDim.x + threadIdx.x;
    if (e >= EE) return;
    int d = load_node(ei, (size_t)EE + e, g_EI64);
    if ((unsigned)d < NN) atomicAdd(&g_DEG[d], 1);
}

__global__ void scanA_kernel() {
    __shared__ int wsum[8];
    int tid = threadIdx.x;
    int base = blockIdx.x * SCB + tid * 4;
    int s = 0;
#pragma unroll
    for (int j = 0; j < 4; j++) { int i = base + j; if (i < NN) s += g_DEG[i]; }
    s = warp_sum_i(s);
    if ((tid & 31) == 0) wsum[tid >> 5] = s;
    __syncthreads();
    if (tid == 0) {
        int t = 0;
#pragma unroll
        for (int w = 0; w < 8; w++) t += wsum[w];
        g_BSUM[blockIdx.x] = t;
    }
}

__global__ void scanB_kernel() {
    __shared__ int sm[4];
    int tid = threadIdx.x, lane = tid & 31, wid = tid >> 5;
    int v = (tid < NBLK) ? g_BSUM[tid] : 0;
    int x = v;
#pragma unroll
    for (int o = 1; o < 32; o <<= 1) {
        int y = __shfl_up_sync(0xffffffffu, x, o);
        if (lane >= o) x += y;
    }
    if (lane == 31) sm[wid] = x;
    __syncthreads();
    int woff = 0;
    for (int w = 0; w < wid; w++) woff += sm[w];
    if (tid < NBLK) g_BOFF[tid] = woff + x - v;
}

__global__ void scanC_kernel() {
    __shared__ int wsum[8];
    int tid = threadIdx.x, lane = tid & 31, wid = tid >> 5;
    int base = blockIdx.x * SCB + tid * 4;
    int a0 = (base + 0 < NN) ? g_DEG[base + 0] : 0;
    int a1 = (base + 1 < NN) ? g_DEG[base + 1] : 0;
    int a2 = (base + 2 < NN) ? g_DEG[base + 2] : 0;
    int a3 = (base + 3 < NN) ? g_DEG[base + 3] : 0;
    int tsum = a0 + a1 + a2 + a3;
    int x = tsum;
#pragma unroll
    for (int o = 1; o < 32; o <<= 1) {
        int y = __shfl_up_sync(0xffffffffu, x, o);
        if (lane >= o) x += y;
    }
    if (lane == 31) wsum[wid] = x;
    __syncthreads();
    int woff = 0;
    for (int w = 0; w < wid; w++) woff += wsum[w];
    int excl = g_BOFF[blockIdx.x] + woff + (x - tsum);
    if (base + 0 < NN) g_ROWPTR[base + 1] = excl + a0;
    if (base + 1 < NN) g_ROWPTR[base + 2] = excl + a0 + a1;
    if (base + 2 < NN) g_ROWPTR[base + 3] = excl + a0 + a1 + a2;
    if (base + 3 < NN) g_ROWPTR[base + 4] = excl + tsum;
    if (blockIdx.x == 0 && tid == 0) g_ROWPTR[0] = 0;
}

__global__ void scatter_kernel(const void* __restrict__ ei) {
    int e = blockIdx.x * blockDim.x + threadIdx.x;
    if (e >= EE) return;
    int is64 = g_EI64;
    int s = load_node(ei, (size_t)e, is64);
    int d = load_node(ei, (size_t)EE + e, is64);
    if ((unsigned)d >= NN || (unsigned)s >= NN) return;
    int pos = g_ROWPTR[d] + atomicAdd(&g_CUR[d], 1);
    if ((unsigned)pos < EE) g_SSRC[pos] = s;
}

// --------------------------- fp16 input conversion ----------------------------
__global__ void cvtx_kernel(const float* __restrict__ x) {
    size_t idx = (size_t)(blockIdx.x * blockDim.x + threadIdx.x) * 4;
    if (idx >= (size_t)NN * FIN) return;
    float4 v = *(const float4*)&x[idx];
    st4h(g_X16, (int)(idx >> 2), v);
}

__global__ void cvtw_kernel(const float* __restrict__ W) {
    int idx = blockIdx.x * blockDim.x + threadIdx.x;   // 0..32767
    if (idx >= FIN * D1) return;
    int k = idx / D1;
    int col = idx % D1;
    // W is [h][k][j]: element = W[(col>>5)*FIN*HID + k*HID + (col&31)]
    float v = W[(size_t)(col >> 5) * (FIN * HID) + (size_t)k * HID + (col & 31)];
    g_W16w[idx] = __float2half_rn(v);
}

// --------------- GEMM1: wmma fp16 tensor cores, 64x128 block tile -------------
// 8 warps: warp (wm,wn) = (warp&1, warp>>1) computes a 32x32 patch (2x2 frags).
__global__ void __launch_bounds__(256) gemm1_kernel() {
    __shared__ __half As[64][24];     // lda=24 (mult of 8)
    __shared__ __half Bs[16][136];    // ldb=136 (mult of 8)
    __shared__ float  Cs[8][16][16];  // per-warp store patch
    int tid = threadIdx.x, warp = tid >> 5, lane = tid & 31;
    int wm = warp & 1, wn = warp >> 1;
    int rowBase = blockIdx.x * 64;
    int colBase = blockIdx.y * 128;
    wmma::fragment<wmma::accumulator, 16, 16, 16, float> c[2][2];
#pragma unroll
    for (int i = 0; i < 2; i++)
#pragma unroll
        for (int j = 0; j < 2; j++)
            wmma::fill_fragment(c[i][j], 0.0f);

    for (int kt = 0; kt < FIN; kt += 16) {
        {   // As: 64 rows x 16 halves (each thread 4 halves)
            int r = tid >> 2;
            int cq = (tid & 3) * 4;
            int gr = rowBase + r;
            uint2 u = make_uint2(0u, 0u);
            if (gr < NN) u = *(const uint2*)&g_X16[(size_t)gr * FIN + kt + cq];
            *(uint2*)&As[r][cq] = u;
        }
#pragma unroll
        for (int p = 0; p < 2; p++) {   // Bs: 16 rows x 128 halves
            int idx = tid + p * 256;
            int k = idx >> 5;
            int cq = (idx & 31) * 4;
            *(uint2*)&Bs[k][cq] = *(const uint2*)&g_W16w[(size_t)(kt + k) * D1 + colBase + cq];
        }
        __syncthreads();
        wmma::fragment<wmma::matrix_a, 16, 16, 16, __half, wmma::row_major> a[2];
        wmma::fragment<wmma::matrix_b, 16, 16, 16, __half, wmma::row_major> b[2];
#pragma unroll
        for (int i = 0; i < 2; i++)
            wmma::load_matrix_sync(a[i], &As[wm * 32 + i * 16][0], 24);
#pragma unroll
        for (int j = 0; j < 2; j++)
            wmma::load_matrix_sync(b[j], &Bs[0][wn * 32 + j * 16], 136);
#pragma unroll
        for (int i = 0; i < 2; i++)
#pragma unroll
            for (int j = 0; j < 2; j++)
                wmma::mma_sync(c[i][j], a[i], b[j], c[i][j]);
        __syncthreads();
    }
    // store: fragment -> smem patch -> fp16 global
#pragma unroll
    for (int i = 0; i < 2; i++)
#pragma unroll
        for (int j = 0; j < 2; j++) {
            wmma::store_matrix_sync(&Cs[warp][0][0], c[i][j], 16, wmma::mem_row_major);
            __syncwarp();
            int r0 = lane >> 1;
            int c0 = (lane & 1) * 8;
            int gr = rowBase + wm * 32 + i * 16 + r0;
            if (gr < NN) {
                float* src = &Cs[warp][r0][c0];
                __half2 h0 = __floats2half2_rn(src[0], src[1]);
                __half2 h1 = __floats2half2_rn(src[2], src[3]);
                __half2 h2 = __floats2half2_rn(src[4], src[5]);
                __half2 h3 = __floats2half2_rn(src[6], src[7]);
                uint4 u;
                u.x = *(unsigned*)&h0; u.y = *(unsigned*)&h1;
                u.z = *(unsigned*)&h2; u.w = *(unsigned*)&h3;
                *(uint4*)&g_H16[(size_t)gr * D1 + colBase + wn * 32 + j * 16 + c0] = u;
            }
            __syncwarp();
        }
}

// ---- GEMM2 (fp16 A-rows) + fused st40; writes O0 (fp32) and O16 (fp16) -------
__global__ void gemm2_kernel(const float* __restrict__ Wout,
                             const float* __restrict__ a_so,
                             const float* __restrict__ a_do) {
    __shared__ float Bs[D1 * NCLS];
    __shared__ float As_[NCLS], Ad_[NCLS];
    int tid = threadIdx.x;
    for (int i = tid; i < D1 * NCLS; i += 256) Bs[i] = Wout[i];
    if (tid < NCLS) { As_[tid] = a_so[tid]; Ad_[tid] = a_do[tid]; }
    __syncthreads();
    int row = blockIdx.x * 256 + tid;
    if (row >= NN) return;
    const __half2* arow = (const __half2*)(g_H16 + (size_t)row * D1);
    float acc[NCLS] = {};
#pragma unroll 2
    for (int k2 = 0; k2 < D1 / 2; k2++) {
        float2 a2 = __half22float2(__ldg(arow + k2));
        const float* b0 = &Bs[(2 * k2) * NCLS];
        const float* b1 = &Bs[(2 * k2 + 1) * NCLS];
#pragma unroll
        for (int c = 0; c < NCLS; c++) acc[c] += a2.x * b0[c] + a2.y * b1[c];
    }
    float* orow = g_O0 + (size_t)row * NCLS;
    __half* orow16 = g_O16 + (size_t)row * NCLS;
    float s = 0.f, t = 0.f;
#pragma unroll
    for (int c = 0; c < NCLS; c++) {
        orow[c] = acc[c];
        orow16[c] = __float2half_rn(acc[c]);
        s += acc[c] * As_[c];
        t += acc[c] * Ad_[c];
    }
    g_S8[row] = s;
    g_T8[row] = t;
}

// --------------------- attention s,t for ALL 8 heads at once ------------------
__global__ void st8_kernel(const float* __restrict__ a_src,
                           const float* __restrict__ a_dst) {
    int gw = blockIdx.x * 8 + (threadIdx.x >> 5);
    int lane = threadIdx.x & 31;
    if (gw >= NN) return;
    const __half* row = g_H16 + (size_t)gw * D1;
#pragma unroll
    for (int h = 0; h < HEADS; h++) {
        float v = __half2float(row[h * HID + lane]);
        float s = warp_sum(v * a_src[h * HID + lane]);
        float t = warp_sum(v * a_dst[h * HID + lane]);
        if (lane == 0) { g_S8[(size_t)gw * 8 + h] = s; g_T8[(size_t)gw * 8 + h] = t; }
    }
}

// ----- 8-head fused attention weights (unnormalized, fp16-stored) + INV --------
__global__ void attn8_kernel() {
    int d = blockIdx.x * 8 + (threadIdx.x >> 5);
    int lane = threadIdx.x & 31;
    if (d >= NN) return;
    int start = g_ROWPTR[d], end = g_ROWPTR[d + 1];
    if (start == end) {
        if (lane == 0) {
            float4 z = make_float4(0.f, 0.f, 0.f, 0.f);
            *(float4*)&g_INV8[(size_t)d * 8] = z;
            *(float4*)&g_INV8[(size_t)d * 8 + 4] = z;
        }
        return;
    }
    float4 ta = *(const float4*)&g_T8[(size_t)d * 8];
    float4 tb = *(const float4*)&g_T8[(size_t)d * 8 + 4];
    float t[8] = {ta.x, ta.y, ta.z, ta.w, tb.x, tb.y, tb.z, tb.w};
    float m[8];
#pragma unroll
    for (int i = 0; i < 8; i++) m[i] = -INFINITY;
    for (int e = start + lane; e < end; e += 32) {
        int s = g_SSRC[e];
        float4 sa = *(const float4*)&g_S8[(size_t)s * 8];
        float4 sb = *(const float4*)&g_S8[(size_t)s * 8 + 4];
        float sv[8] = {sa.x, sa.y, sa.z, sa.w, sb.x, sb.y, sb.z, sb.w};
#pragma unroll
        for (int i = 0; i < 8; i++) {
            float ev = sv[i] + t[i];
            ev = (ev >= 0.f) ? ev : LRA * ev;
            m[i] = fmaxf(m[i], ev);
        }
    }
#pragma unroll
    for (int i = 0; i < 8; i++) m[i] = warp_max(m[i]);
    float u[8] = {};
    for (int e = start + lane; e < end; e += 32) {
        int s = g_SSRC[e];
        float4 sa = *(const float4*)&g_S8[(size_t)s * 8];
        float4 sb = *(const float4*)&g_S8[(size_t)s * 8 + 4];
        float sv[8] = {sa.x, sa.y, sa.z, sa.w, sb.x, sb.y, sb.z, sb.w};
        float p[8];
#pragma unroll
        for (int i = 0; i < 8; i++) {
            float ev = sv[i] + t[i];
            ev = (ev >= 0.f) ? ev : LRA * ev;
            p[i] = expf(ev - m[i]);
            u[i] += p[i];
        }
        st4h(g_W16[0], e, make_float4(p[0], p[1], p[2], p[3]));
        st4h(g_W16[1], e, make_float4(p[4], p[5], p[6], p[7]));
    }
#pragma unroll
    for (int i = 0; i < 8; i++) u[i] = warp_sum(u[i]);
    if (lane == 0) {
        *(float4*)&g_INV8[(size_t)d * 8] =
            make_float4(1.f / (u[0] + 1e-16f), 1.f / (u[1] + 1e-16f),
                        1.f / (u[2] + 1e-16f), 1.f / (u[3] + 1e-16f));
        *(float4*)&g_INV8[(size_t)d * 8 + 4] =
            make_float4(1.f / (u[4] + 1e-16f), 1.f / (u[5] + 1e-16f),
                        1.f / (u[6] + 1e-16f), 1.f / (u[7] + 1e-16f));
    }
}

// --------- 4-head fused diffusion hop, fp16 gathers + fp16 weights ------------
__global__ void hop4_kernel(int g, int mode) {
    int d = blockIdx.x * 8 + (threadIdx.x >> 5);
    int lane = threadIdx.x & 31;
    if (d >= NN) return;
    int h = lane >> 3;
    int start = g_ROWPTR[d], end = g_ROWPTR[d + 1];
    const __half* wb = g_W16[g];
    float4 acc = make_float4(0.f, 0.f, 0.f, 0.f);
    int e = start;
    for (; e + 4 <= end; e += 4) {
        int s0 = g_SSRC[e], s1 = g_SSRC[e + 1], s2 = g_SSRC[e + 2], s3 = g_SSRC[e + 3];
        float4 w0 = ld4h(wb, e);
        float4 w1 = ld4h(wb, e + 1);
        float4 w2 = ld4h(wb, e + 2);
        float4 w3 = ld4h(wb, e + 3);
        const __half *r0, *r1, *r2, *r3;
        if (mode == 0) {
            r0 = g_H16 + (size_t)s0 * D1 + g * 128;
            r1 = g_H16 + (size_t)s1 * D1 + g * 128;
            r2 = g_H16 + (size_t)s2 * D1 + g * 128;
            r3 = g_H16 + (size_t)s3 * D1 + g * 128;
        } else {
            r0 = g_FA16 + (size_t)s0 * 128;
            r1 = g_FA16 + (size_t)s1 * 128;
            r2 = g_FA16 + (size_t)s2 * 128;
            r3 = g_FA16 + (size_t)s3 * 128;
        }
        float4 v0 = ld4h(r0, lane), v1 = ld4h(r1, lane);
        float4 v2 = ld4h(r2, lane), v3 = ld4h(r3, lane);
        float wv0 = sel4(w0, h), wv1 = sel4(w1, h), wv2 = sel4(w2, h), wv3 = sel4(w3, h);
        acc.x += wv0 * v0.x + wv1 * v1.x + wv2 * v2.x + wv3 * v3.x;
        acc.y += wv0 * v0.y + wv1 * v1.y + wv2 * v2.y + wv3 * v3.y;
        acc.z += wv0 * v0.z + wv1 * v1.z + wv2 * v2.z + wv3 * v3.z;
        acc.w += wv0 * v0.w + wv1 * v1.w + wv2 * v2.w + wv3 * v3.w;
    }
    for (; e < end; e++) {
        int s0 = g_SSRC[e];
        float4 w0 = ld4h(wb, e);
        const __half* r0 = (mode == 0)
            ? g_H16 + (size_t)s0 * D1 + g * 128
            : g_FA16 + (size_t)s0 * 128;
        float4 v0 = ld4h(r0, lane);
        float wv0 = sel4(w0, h);
        acc.x += wv0 * v0.x; acc.y += wv0 * v0.y;
        acc.z += wv0 * v0.z; acc.w += wv0 * v0.w;
    }
    float4 inv4 = *(const float4*)&g_INV8[(size_t)d * 8 + g * 4];
    float invv = sel4(inv4, h);
    __half* h0p = g_H16 + (size_t)d * D1 + g * 128;
    float4 h0v = ld4h(h0p, lane);
    float4 v;
    v.x = ONE_MB * acc.x * invv + BETA * h0v.x;
    v.y = ONE_MB * acc.y * invv + BETA * h0v.y;
    v.z = ONE_MB * acc.z * invv + BETA * h0v.z;
    v.w = ONE_MB * acc.w * invv + BETA * h0v.w;
    if (mode == 0) {
        st4h(g_FA16 + (size_t)d * 128, lane, v);
    } else {
        v.x = (v.x > 0.f) ? v.x : expm1f(v.x);
        v.y = (v.y > 0.f) ? v.y : expm1f(v.y);
        v.z = (v.z > 0.f) ? v.z : expm1f(v.z);
        v.w = (v.w > 0.f) ? v.w : expm1f(v.w);
        st4h(h0p, lane, v);
    }
}

// ------------------------------ output layer -----------------------------------
__global__ void attn_w_kernel() {      // normalized weights into g_W16[0] (fp16)
    int d = blockIdx.x * 8 + (threadIdx.x >> 5);
    int lane = threadIdx.x & 31;
    if (d >= NN) return;
    int start = g_ROWPTR[d], end = g_ROWPTR[d + 1];
    if (start == end) return;
    __half* wb = g_W16[0];
    float td = g_T8[d];
    float m = -INFINITY;
    for (int e = start + lane; e < end; e += 32) {
        float ev = g_S8[g_SSRC[e]] + td;
        ev = (ev >= 0.f) ? ev : LRA * ev;
        m = fmaxf(m, ev);
    }
    m = warp_max(m);
    float sum = 0.f;
    for (int e = start + lane; e < end; e += 32) {
        float ev = g_S8[g_SSRC[e]] + td;
        ev = (ev >= 0.f) ? ev : LRA * ev;
        sum += expf(ev - m);
    }
    sum = warp_sum(sum);
    float inv = 1.f / (sum + 1e-16f);
    for (int e = start + lane; e < end; e += 32) {
        float ev = g_S8[g_SSRC[e]] + td;
        ev = (ev >= 0.f) ? ev : LRA * ev;
        wb[e] = __float2half_rn(expf(ev - m) * inv);
    }
}

__global__ void hop40_kernel(int mode, float* __restrict__ out) {
    int d = blockIdx.x * 8 + (threadIdx.x >> 5);
    int lane = threadIdx.x & 31;
    if (d >= NN) return;
    int start = g_ROWPTR[d], end = g_ROWPTR[d + 1];
    float acca = 0.f, accb = 0.f;
    bool hi = (lane < 8);
    const __half* base = (mode == 0) ? g_O16 : g_GA16;
    const __half* wb = g_W16[0];
    int e = start;
    for (; e + 4 <= end; e += 4) {
        int s0 = g_SSRC[e], s1 = g_SSRC[e + 1], s2 = g_SSRC[e + 2], s3 = g_SSRC[e + 3];
        float w0 = __half2float(wb[e]);
        float w1 = __half2float(wb[e + 1]);
        float w2 = __half2float(wb[e + 2]);
        float w3 = __half2float(wb[e + 3]);
        const __half* r0 = base + (size_t)s0 * NCLS;
        const __half* r1 = base + (size_t)s1 * NCLS;
        const __half* r2 = base + (size_t)s2 * NCLS;
        const __half* r3 = base + (size_t)s3 * NCLS;
        acca += w0 * __half2float(r0[lane]) + w1 * __half2float(r1[lane])
              + w2 * __half2float(r2[lane]) + w3 * __half2float(r3[lane]);
        if (hi)
            accb += w0 * __half2float(r0[32 + lane]) + w1 * __half2float(r1[32 + lane])
                  + w2 * __half2float(r2[32 + lane]) + w3 * __half2float(r3[32 + lane]);
    }
    for (; e < end; e++) {
        int s = g_SSRC[e];
        float w = __half2float(wb[e]);
        const __half* row = base + (size_t)s * NCLS;
        acca += w * __half2float(row[lane]);
        if (hi) accb += w * __half2float(row[32 + lane]);
    }
    const float* h0row = g_O0 + (size_t)d * NCLS;
    float va = ONE_MB * acca + BETA * h0row[lane];
    float vb = hi ? (ONE_MB * accb + BETA * h0row[32 + lane]) : 0.f;
    if (mode == 0) {
        __half* orow = g_GA16 + (size_t)d * NCLS;
        orow[lane] = __float2half_rn(va);
        if (hi) orow[32 + lane] = __float2half_rn(vb);
    } else {
        float ea = (va > 0.f) ? va : expm1f(va);
        float eb = hi ? ((vb > 0.f) ? vb : expm1f(vb)) : -INFINITY;
        float mx = warp_max(fmaxf(ea, eb));
        float se = expf(ea - mx) + (hi ? expf(eb - mx) : 0.f);
        se = warp_sum(se);
        float lse = mx + logf(se);
        float* orow = out + (size_t)d * NCLS;
        orow[lane] = ea - lse;
        if (hi) orow[32 + lane] = eb - lse;
    }
}

// --------------------------------- launch -------------------------------------
extern "C" void kernel_launch(void* const* d_in, const int* in_sizes, int n_in,
                              void* d_out, int out_size) {
    const float* x     = (const float*)d_in[0];
    const void*  ei    = d_in[1];
    const float* W     = (const float*)d_in[2];
    const float* a_src = (const float*)d_in[3];
    const float* a_dst = (const float*)d_in[4];
    const float* Wout  = (const float*)d_in[5];
    const float* a_so  = (const float*)d_in[6];
    const float* a_do  = (const float*)d_in[7];
    float*       out   = (float*)d_out;

    const int NWARP_GRID = (NN + 7) / 8;
    const int EGRID = (EE + 255) / 256;
    const int NGRID = (NN + 255) / 256;

    sniff_kernel<<<1, 256>>>((const int*)ei);
    zero_counts_kernel<<<NGRID, 256>>>();
    build_deg_kernel<<<EGRID, 256>>>(ei);
    scanA_kernel<<<NBLK, 256>>>();
    scanB_kernel<<<1, 128>>>();
    scanC_kernel<<<NBLK, 256>>>();
    scatter_kernel<<<EGRID, 256>>>(ei);

    cvtx_kernel<<<(NN * FIN / 4 + 255) / 256, 256>>>(x);
    cvtw_kernel<<<(FIN * D1 + 255) / 256, 256>>>(W);
    gemm1_kernel<<<dim3((NN + 63) / 64, D1 / 128), 256>>>();
    st8_kernel<<<NWARP_GRID, 256>>>(a_src, a_dst);
    attn8_kernel<<<NWARP_GRID, 256>>>();

    for (int g = 0; g < 2; g++) {
        hop4_kernel<<<NWARP_GRID, 256>>>(g, 0);
        hop4_kernel<<<NWARP_GRID, 256>>>(g, 1);
    }

    gemm2_kernel<<<(NN + 255) / 256, 256>>>(Wout, a_so, a_do);

    attn_w_kernel<<<NWARP_GRID, 256>>>();
    hop40_kernel<<<NWARP_GRID, 256>>>(0, nullptr);
    hop40_kernel<<<NWARP_GRID, 256>>>(1, out);
}